// round 3
// baseline (speedup 1.0000x reference)
#include <cuda_runtime.h>
#include <math.h>

// Fixed problem shapes
#define CL1 32896   // total ragged tokens = 256*257/2
#define CB  256     // batches
#define CD  256     // hidden
#define CH  4       // heads
#define CHD 64      // head dim
#define BM  32      // tokens per GEMM block
#define XST 36      // xsT smem stride (float4-aligned, low-conflict transpose writes)

// Scratch (device globals; no allocation allowed)
__device__ int   g_starts[CB];
__device__ int   g_pos[CL1];
__device__ float g_qcat[CL1 * CD];
__device__ float g_Q[CL1 * CD];
__device__ float g_K[CL1 * CD];
__device__ float g_V[CL1 * CD];
__device__ float g_ctx[CL1 * CD];
__device__ float g_h[CL1 * CD];

// ---------------------------------------------------------------------------
// Kernel 0: ragged index construction (starts + local positions)
// ---------------------------------------------------------------------------
__global__ void k_index(const int* __restrict__ sl) {
    __shared__ int st[CB];
    int tid = threadIdx.x;
    if (tid == 0) {
        int a = 0;
        for (int b = 0; b < CB; b++) { st[b] = a; a += sl[b]; }
    }
    __syncthreads();
    int s = st[tid];
    int len = sl[tid];
    g_starts[tid] = s;
    for (int i = 0; i < len; i++) g_pos[s + i] = i;
}

// ---------------------------------------------------------------------------
// Shared GEMM mainloop: acc[8][4] += xsT^T @ W  over K=256.
// Thread tile: 8 tokens (mg) x 4 cols (cg). a = broadcast LDS.128 x2,
// b = 1 coalesced LDG.128. 3 mem instr per 32 FMA.
// ---------------------------------------------------------------------------
__device__ __forceinline__ void gemm_k256(
    const float* __restrict__ xsT, const float* __restrict__ W,
    int cg, int mg, float acc[8][4]) {
    const float* Wp = W + cg * 4;
    const float* Ap = xsT + mg * 8;
#pragma unroll 4
    for (int k = 0; k < 256; k++) {
        float4 b = *(const float4*)(Wp + k * CD);
        float4 a0 = *(const float4*)(Ap + k * XST);
        float4 a1 = *(const float4*)(Ap + k * XST + 4);
        float a[8] = {a0.x, a0.y, a0.z, a0.w, a1.x, a1.y, a1.z, a1.w};
#pragma unroll
        for (int i = 0; i < 8; i++) {
            acc[i][0] = fmaf(a[i], b.x, acc[i][0]);
            acc[i][1] = fmaf(a[i], b.y, acc[i][1]);
            acc[i][2] = fmaf(a[i], b.z, acc[i][2]);
            acc[i][3] = fmaf(a[i], b.w, acc[i][3]);
        }
    }
}

// ---------------------------------------------------------------------------
// Kernel 1: fused (emb + pos_table[p+SHIFT]) @ W + b
// ---------------------------------------------------------------------------
template <int SHIFT, bool SAVEQ>
__global__ __launch_bounds__(256, 1) void k_proj(
    const float* __restrict__ emb, const float* __restrict__ pt,
    const float* __restrict__ W, const float* __restrict__ bias,
    float* __restrict__ out) {
    __shared__ float xsT[CD * XST];
    __shared__ int spos[BM];
    int t0 = blockIdx.x * BM, tid = threadIdx.x;
    if (tid < BM) spos[tid] = g_pos[t0 + tid];
    __syncthreads();
    int c = tid;
#pragma unroll
    for (int t = 0; t < BM; t += 4) {
        float4 v;
        v.x = emb[(t0 + t + 0) * CD + c] + pt[(spos[t + 0] + SHIFT) * CD + c];
        v.y = emb[(t0 + t + 1) * CD + c] + pt[(spos[t + 1] + SHIFT) * CD + c];
        v.z = emb[(t0 + t + 2) * CD + c] + pt[(spos[t + 2] + SHIFT) * CD + c];
        v.w = emb[(t0 + t + 3) * CD + c] + pt[(spos[t + 3] + SHIFT) * CD + c];
        if (SAVEQ) {
            g_qcat[(t0 + t + 0) * CD + c] = v.x;
            g_qcat[(t0 + t + 1) * CD + c] = v.y;
            g_qcat[(t0 + t + 2) * CD + c] = v.z;
            g_qcat[(t0 + t + 3) * CD + c] = v.w;
        }
        *(float4*)&xsT[c * XST + t] = v;
    }
    __syncthreads();
    int cg = tid & 63, mg = tid >> 6;
    float acc[8][4];
#pragma unroll
    for (int i = 0; i < 8; i++)
#pragma unroll
        for (int j = 0; j < 4; j++) acc[i][j] = 0.f;
    gemm_k256(xsT, W, cg, mg, acc);
    float4 b4 = *(const float4*)(bias + cg * 4);
#pragma unroll
    for (int i = 0; i < 8; i++) {
        float4 o = make_float4(acc[i][0] + b4.x, acc[i][1] + b4.y,
                               acc[i][2] + b4.z, acc[i][3] + b4.w);
        *(float4*)&out[(t0 + mg * 8 + i) * CD + cg * 4] = o;
    }
}

// ---------------------------------------------------------------------------
// Kernel 2: zero-attention per (batch, head). Warp = 4 query rows per pass.
// K/V in smem as XOR-swizzled float4 chunks: chunk(j,d4) = j*16 + (d4^(j&7))
// -> conflict-free LDS.128 both for per-key (scores) and per-dim (ctx) access.
// ---------------------------------------------------------------------------
__global__ __launch_bounds__(256, 1) void k_attn(const int* __restrict__ sl) {
    extern __shared__ float sm[];
    float4* Ks   = (float4*)sm;               // 256*16 chunks
    float4* Vs   = Ks + 256 * 16;             // 256*16 chunks
    float*  prob = (float*)(Vs + 256 * 16);   // 8 warps * 4 * 256
    float*  qb   = prob + 8 * 4 * 256;        // 8 warps * 4 * 64

    int b = blockIdx.x, h = blockIdx.y;
    int L = sl[b], start = g_starts[b];
    int tid = threadIdx.x;
    int hoff = h * CHD;

    for (int qd = tid; qd < L * 16; qd += 256) {
        int j = qd >> 4, d4 = qd & 15;
        int sw = (j << 4) | (d4 ^ (j & 7));
        Ks[sw] = *(const float4*)&g_K[(start + j) * CD + hoff + (d4 << 2)];
        Vs[sw] = *(const float4*)&g_V[(start + j) * CD + hoff + (d4 << 2)];
    }
    __syncthreads();

    int w = tid >> 5, lane = tid & 31;
    float* pw = prob + w * 1024;
    float* qw = qb + w * 256;
    int lsw = lane & 7;

    for (int q0 = w * 4; q0 < L; q0 += 32) {
        int nq = min(4, L - q0);
        // stage 4 query rows
#pragma unroll
        for (int qi = 0; qi < 4; qi++) {
            if (qi < nq) {
                const float* qp = &g_Q[(start + q0 + qi) * CD + hoff];
                qw[qi * 64 + lane] = qp[lane];
                qw[qi * 64 + 32 + lane] = qp[32 + lane];
            }
        }
        __syncwarp();

        // scores: lane owns keys j = lane + 32*jj
        int jrow[8];
#pragma unroll
        for (int jj = 0; jj < 8; jj++) {
            int j = lane + 32 * jj;
            jrow[jj] = (j < L ? j : 0) << 4;
        }
        float s[4][8];
#pragma unroll
        for (int qi = 0; qi < 4; qi++)
#pragma unroll
            for (int jj = 0; jj < 8; jj++) s[qi][jj] = 0.f;
#pragma unroll 4
        for (int d4 = 0; d4 < 16; d4++) {
            float4 kf[8];
            int swd = d4 ^ lsw;
#pragma unroll
            for (int jj = 0; jj < 8; jj++) kf[jj] = Ks[jrow[jj] + swd];
#pragma unroll
            for (int qi = 0; qi < 4; qi++) {
                float4 qv = *(float4*)&qw[qi * 64 + (d4 << 2)];
#pragma unroll
                for (int jj = 0; jj < 8; jj++) {
                    s[qi][jj] = fmaf(qv.x, kf[jj].x, s[qi][jj]);
                    s[qi][jj] = fmaf(qv.y, kf[jj].y, s[qi][jj]);
                    s[qi][jj] = fmaf(qv.z, kf[jj].z, s[qi][jj]);
                    s[qi][jj] = fmaf(qv.w, kf[jj].w, s[qi][jj]);
                }
            }
        }

        // softmax per query (zero-slot: extra key with score 0, value 0)
        float inv[4];
#pragma unroll
        for (int qi = 0; qi < 4; qi++) {
            if (qi >= nq) continue;
            float m = 0.f;
#pragma unroll
            for (int jj = 0; jj < 8; jj++) {
                int j = lane + 32 * jj;
                s[qi][jj] = (j < L) ? s[qi][jj] * 0.125f : -1e30f;
                m = fmaxf(m, s[qi][jj]);
            }
#pragma unroll
            for (int o = 16; o; o >>= 1) m = fmaxf(m, __shfl_xor_sync(0xffffffffu, m, o));
            float ds = (lane == 0) ? __expf(0.f - m) : 0.f;
#pragma unroll
            for (int jj = 0; jj < 8; jj++) {
                int j = lane + 32 * jj;
                if (j < L) {
                    float p = __expf(s[qi][jj] - m);
                    pw[qi * 256 + j] = p;
                    ds += p;
                }
            }
#pragma unroll
            for (int o = 16; o; o >>= 1) ds += __shfl_xor_sync(0xffffffffu, ds, o);
            inv[qi] = 1.f / ds;
        }
        __syncwarp();

        // ctx: lane owns dim chunk d4c (4 dims) and j-parity
        int d4c = lane & 15, par = lane >> 4;
        float4 cacc[4];
#pragma unroll
        for (int qi = 0; qi < 4; qi++) cacc[qi] = make_float4(0.f, 0.f, 0.f, 0.f);
        for (int j = par; j < L; j += 2) {
            float4 vv = Vs[(j << 4) + (d4c ^ (j & 7))];
#pragma unroll
            for (int qi = 0; qi < 4; qi++) {
                float p = pw[qi * 256 + j];
                cacc[qi].x = fmaf(p, vv.x, cacc[qi].x);
                cacc[qi].y = fmaf(p, vv.y, cacc[qi].y);
                cacc[qi].z = fmaf(p, vv.z, cacc[qi].z);
                cacc[qi].w = fmaf(p, vv.w, cacc[qi].w);
            }
        }
#pragma unroll
        for (int qi = 0; qi < 4; qi++) {
            cacc[qi].x += __shfl_xor_sync(0xffffffffu, cacc[qi].x, 16);
            cacc[qi].y += __shfl_xor_sync(0xffffffffu, cacc[qi].y, 16);
            cacc[qi].z += __shfl_xor_sync(0xffffffffu, cacc[qi].z, 16);
            cacc[qi].w += __shfl_xor_sync(0xffffffffu, cacc[qi].w, 16);
            if (qi < nq && par == 0) {
                float4 o = make_float4(cacc[qi].x * inv[qi], cacc[qi].y * inv[qi],
                                       cacc[qi].z * inv[qi], cacc[qi].w * inv[qi]);
                *(float4*)&g_ctx[(start + q0 + qi) * CD + hoff + (d4c << 2)] = o;
            }
        }
        __syncwarp();
    }
}

// ---------------------------------------------------------------------------
// Kernel 3: h = LayerNorm(ctx @ wo + bo + q_cat)
// ---------------------------------------------------------------------------
__global__ __launch_bounds__(256, 1) void k_selfout(
    const float* __restrict__ wo, const float* __restrict__ bo,
    const float* __restrict__ lng, const float* __restrict__ lnb) {
    __shared__ float xsT[CD * XST];       // reused as hb[32][256] after mainloop
    __shared__ float mu[BM], rsg[BM];
    int t0 = blockIdx.x * BM, tid = threadIdx.x;
    int c = tid;
#pragma unroll
    for (int t = 0; t < BM; t += 4) {
        float4 v;
        v.x = g_ctx[(t0 + t + 0) * CD + c];
        v.y = g_ctx[(t0 + t + 1) * CD + c];
        v.z = g_ctx[(t0 + t + 2) * CD + c];
        v.w = g_ctx[(t0 + t + 3) * CD + c];
        *(float4*)&xsT[c * XST + t] = v;
    }
    __syncthreads();
    int cg = tid & 63, mg = tid >> 6;
    float acc[8][4];
#pragma unroll
    for (int i = 0; i < 8; i++)
#pragma unroll
        for (int j = 0; j < 4; j++) acc[i][j] = 0.f;
    gemm_k256(xsT, wo, cg, mg, acc);
    __syncthreads();   // done with xsT, reuse as hb
    float* hb = xsT;
    float4 b4 = *(const float4*)(bo + cg * 4);
#pragma unroll
    for (int i = 0; i < 8; i++) {
        int t = t0 + mg * 8 + i;
        float4 qc = *(const float4*)&g_qcat[t * CD + cg * 4];
        acc[i][0] += b4.x + qc.x;
        acc[i][1] += b4.y + qc.y;
        acc[i][2] += b4.z + qc.z;
        acc[i][3] += b4.w + qc.w;
        *(float4*)&hb[(mg * 8 + i) * CD + cg * 4] =
            make_float4(acc[i][0], acc[i][1], acc[i][2], acc[i][3]);
    }
    __syncthreads();
    int w = tid >> 5, lane = tid & 31;
#pragma unroll
    for (int rr = 0; rr < 4; rr++) {
        int r = w * 4 + rr;
        float s1 = 0.f, s2 = 0.f;
#pragma unroll
        for (int cc = 0; cc < CD; cc += 32) {
            float v = hb[r * CD + cc + lane];
            s1 += v; s2 += v * v;
        }
#pragma unroll
        for (int o = 16; o; o >>= 1) {
            s1 += __shfl_xor_sync(0xffffffffu, s1, o);
            s2 += __shfl_xor_sync(0xffffffffu, s2, o);
        }
        if (lane == 0) {
            float mm = s1 * (1.f / CD);
            mu[r] = mm;
            rsg[r] = rsqrtf(s2 * (1.f / CD) - mm * mm + 1e-12f);
        }
    }
    __syncthreads();
    float4 g4 = *(const float4*)(lng + cg * 4);
    float4 bb4 = *(const float4*)(lnb + cg * 4);
#pragma unroll
    for (int i = 0; i < 8; i++) {
        int r = mg * 8 + i;
        float m = mu[r], rs = rsg[r];
        float4 o = make_float4((acc[i][0] - m) * rs * g4.x + bb4.x,
                               (acc[i][1] - m) * rs * g4.y + bb4.y,
                               (acc[i][2] - m) * rs * g4.z + bb4.z,
                               (acc[i][3] - m) * rs * g4.w + bb4.w);
        *(float4*)&g_h[(t0 + r) * CD + cg * 4] = o;
    }
}

// ---------------------------------------------------------------------------
// Kernel 4: out = gelu(concat(h, q_cat) @ wm + bm), K=512 in two phases
// ---------------------------------------------------------------------------
__global__ __launch_bounds__(256, 1) void k_merge(
    const float* __restrict__ wm, const float* __restrict__ bm,
    float* __restrict__ out) {
    __shared__ float xsT[CD * XST];
    int t0 = blockIdx.x * BM, tid = threadIdx.x;
    int cg = tid & 63, mg = tid >> 6;
    int c = tid;
    float acc[8][4];
#pragma unroll
    for (int i = 0; i < 8; i++)
#pragma unroll
        for (int j = 0; j < 4; j++) acc[i][j] = 0.f;

    // phase A: h part (wm rows 0..255)
#pragma unroll
    for (int t = 0; t < BM; t += 4) {
        float4 v;
        v.x = g_h[(t0 + t + 0) * CD + c];
        v.y = g_h[(t0 + t + 1) * CD + c];
        v.z = g_h[(t0 + t + 2) * CD + c];
        v.w = g_h[(t0 + t + 3) * CD + c];
        *(float4*)&xsT[c * XST + t] = v;
    }
    __syncthreads();
    gemm_k256(xsT, wm, cg, mg, acc);
    __syncthreads();

    // phase B: qcat part (wm rows 256..511)
#pragma unroll
    for (int t = 0; t < BM; t += 4) {
        float4 v;
        v.x = g_qcat[(t0 + t + 0) * CD + c];
        v.y = g_qcat[(t0 + t + 1) * CD + c];
        v.z = g_qcat[(t0 + t + 2) * CD + c];
        v.w = g_qcat[(t0 + t + 3) * CD + c];
        *(float4*)&xsT[c * XST + t] = v;
    }
    __syncthreads();
    gemm_k256(xsT, wm + 256 * CD, cg, mg, acc);

    float4 b4 = *(const float4*)(bm + cg * 4);
#pragma unroll
    for (int i = 0; i < 8; i++) {
        float x0 = acc[i][0] + b4.x, x1 = acc[i][1] + b4.y;
        float x2 = acc[i][2] + b4.z, x3 = acc[i][3] + b4.w;
        const float r2 = 0.70710678118654752440f;
        float4 o = make_float4(0.5f * x0 * (1.f + erff(x0 * r2)),
                               0.5f * x1 * (1.f + erff(x1 * r2)),
                               0.5f * x2 * (1.f + erff(x2 * r2)),
                               0.5f * x3 * (1.f + erff(x3 * r2)));
        *(float4*)&out[(t0 + mg * 8 + i) * CD + cg * 4] = o;
    }
}

// ---------------------------------------------------------------------------
extern "C" void kernel_launch(void* const* d_in, const int* in_sizes, int n_in,
                              void* d_out, int out_size) {
    const float* qe  = (const float*)d_in[0];
    const float* ke  = (const float*)d_in[1];
    const float* ve  = (const float*)d_in[2];
    const float* pt  = (const float*)d_in[3];
    const float* wq  = (const float*)d_in[4];
    const float* bq  = (const float*)d_in[5];
    const float* wk  = (const float*)d_in[6];
    const float* bk  = (const float*)d_in[7];
    const float* wv  = (const float*)d_in[8];
    const float* bv  = (const float*)d_in[9];
    const float* wo  = (const float*)d_in[10];
    const float* bo  = (const float*)d_in[11];
    const float* lng = (const float*)d_in[12];
    const float* lnb = (const float*)d_in[13];
    const float* wm  = (const float*)d_in[14];
    const float* bm  = (const float*)d_in[15];
    const int*   sl  = (const int*)d_in[16];
    float* out = (float*)d_out;

    float *gQ, *gK, *gV;
    cudaGetSymbolAddress((void**)&gQ, g_Q);
    cudaGetSymbolAddress((void**)&gK, g_K);
    cudaGetSymbolAddress((void**)&gV, g_V);

    constexpr int GB = CL1 / BM;  // 1028 blocks, exact

    k_index<<<1, CB>>>(sl);
    k_proj<1, true ><<<GB, 256>>>(qe, pt, wq, bq, gQ);
    k_proj<0, false><<<GB, 256>>>(ke, pt, wk, bk, gK);
    k_proj<0, false><<<GB, 256>>>(ve, pt, wv, bv, gV);

    // attn smem: K(16384) + V(16384) + probs(8192) + qb(2048) floats
    constexpr size_t ASM = (size_t)(16384 + 16384 + 8192 + 2048) * sizeof(float);
    cudaFuncSetAttribute(k_attn, cudaFuncAttributeMaxDynamicSharedMemorySize, (int)ASM);
    k_attn<<<dim3(CB, CH), 256, ASM>>>(sl);

    k_selfout<<<GB, 256>>>(wo, bo, lng, lnb);
    k_merge<<<GB, 256>>>(wm, bm, out);
}

// round 5
// speedup vs baseline: 1.5238x; 1.5238x over previous
#include <cuda_runtime.h>
#include <cuda_bf16.h>
#include <math.h>
#include <stdint.h>

#define CL1 32896
#define CB  256
#define CD  256
#define CH  4
#define CHD 64
#define TM  128
#define TN  128
#define GBX 257     // CL1 / TM

__device__ int   g_starts[CB];
__device__ int   g_pos[CL1];
__device__ int   g_order[CB];
__device__ float g_qcat[CL1 * CD];
__device__ float g_Q[CL1 * CD];      // also reused as selfout GEMM tmp
__device__ float g_K[CL1 * CD];
__device__ float g_V[CL1 * CD];
__device__ float g_ctx[CL1 * CD];
__device__ float g_h[CL1 * CD];
__device__ __nv_bfloat16 g_wtq_h[CD * CD], g_wtq_l[CD * CD];
__device__ __nv_bfloat16 g_wtk_h[CD * CD], g_wtk_l[CD * CD];
__device__ __nv_bfloat16 g_wtv_h[CD * CD], g_wtv_l[CD * CD];
__device__ __nv_bfloat16 g_wto_h[CD * CD], g_wto_l[CD * CD];
__device__ __nv_bfloat16 g_wtm_h[2 * CD * CD], g_wtm_l[2 * CD * CD];

__device__ __forceinline__ uint32_t smem_u32(const void* p) {
    return (uint32_t)__cvta_generic_to_shared(p);
}
__device__ __forceinline__ uint32_t swz(uint32_t off) {
    return off ^ ((off >> 3) & 0x70);
}
__device__ __forceinline__ void ldsm4(uint32_t r[4], uint32_t addr) {
    asm volatile("ldmatrix.sync.aligned.m8n8.x4.shared.b16 {%0,%1,%2,%3}, [%4];"
                 : "=r"(r[0]), "=r"(r[1]), "=r"(r[2]), "=r"(r[3]) : "r"(addr));
}
__device__ __forceinline__ void mma_bf16(float d[4], const uint32_t a[4],
                                         uint32_t b0, uint32_t b1) {
    asm volatile("mma.sync.aligned.m16n8k16.row.col.f32.bf16.bf16.f32 "
                 "{%0,%1,%2,%3}, {%4,%5,%6,%7}, {%8,%9}, {%0,%1,%2,%3};"
                 : "+f"(d[0]), "+f"(d[1]), "+f"(d[2]), "+f"(d[3])
                 : "r"(a[0]), "r"(a[1]), "r"(a[2]), "r"(a[3]), "r"(b0), "r"(b1));
}

// ---------------------------------------------------------------------------
__global__ void k_index(const int* __restrict__ sl) {
    __shared__ int st[CB];
    int tid = threadIdx.x;
    if (tid == 0) {
        int a = 0;
        for (int b = 0; b < CB; b++) { st[b] = a; a += sl[b]; }
    }
    __syncthreads();
    int s = st[tid], len = sl[tid];
    g_starts[tid] = s;
    g_order[CB - len] = tid;
    for (int i = 0; i < len; i++) g_pos[s + i] = i;
}

// transpose + bf16 hi/lo split: WT[n][k] = W[k][n]
__global__ void k_wt(const float* __restrict__ wq, const float* __restrict__ wk,
                     const float* __restrict__ wv, const float* __restrict__ wo,
                     const float* __restrict__ wm) {
    __shared__ float t[32][33];
    int z = blockIdx.z;
    const float* W; __nv_bfloat16* oh; __nv_bfloat16* ol; int K;
    switch (z) {
        case 0: W = wq; oh = g_wtq_h; ol = g_wtq_l; K = 256; break;
        case 1: W = wk; oh = g_wtk_h; ol = g_wtk_l; K = 256; break;
        case 2: W = wv; oh = g_wtv_h; ol = g_wtv_l; K = 256; break;
        case 3: W = wo; oh = g_wto_h; ol = g_wto_l; K = 256; break;
        default: W = wm; oh = g_wtm_h; ol = g_wtm_l; K = 512; break;
    }
    int k0 = blockIdx.x * 32, n0 = blockIdx.y * 32;
    if (k0 >= K) return;
    int tx = threadIdx.x, ty = threadIdx.y;
#pragma unroll
    for (int i = 0; i < 4; i++)
        t[ty + 8 * i][tx] = W[(size_t)(k0 + ty + 8 * i) * CD + n0 + tx];
    __syncthreads();
#pragma unroll
    for (int i = 0; i < 4; i++) {
        int rr = ty + 8 * i;
        float v = t[tx][rr];
        __nv_bfloat16 h = __float2bfloat16_rn(v);
        float l = v - __bfloat162float(h);
        oh[(size_t)(n0 + rr) * K + k0 + tx] = h;
        ol[(size_t)(n0 + rr) * K + k0 + tx] = __float2bfloat16_rn(l);
    }
}

// ---------------------------------------------------------------------------
// mma.sync bf16-split GEMM. CTA 512 thr (16 warps, 4Mx4N), tile 128x128.
// K chunks of 64 in smem: Ah(16K) Al(16K) Bh(16K) Bl(16K) swizzled.
// MODE 0: A = emb + pos_table[pos+shift] (opt save qcat); out = A@W + bias
// MODE 1: A = g_ctx; out = A@Wo (raw, LN in separate kernel)
// MODE 2: A = [g_h | g_qcat] (K=512); out = gelu(A@Wm + bias)
// ---------------------------------------------------------------------------
template <int MODE>
__global__ __launch_bounds__(512, 1)
void k_gemm(const float* __restrict__ asrc, const float* __restrict__ pt,
            const __nv_bfloat16* __restrict__ Bh_g, const __nv_bfloat16* __restrict__ Bl_g,
            const float* __restrict__ bias, float* __restrict__ outp,
            int shift, int saveq) {
    extern __shared__ char smc[];
    const uint32_t su = smem_u32(smc);
    constexpr int KW = (MODE == 2) ? 512 : 256;
    constexpr int NCH = KW / 64;
    const int t0 = blockIdx.x * TM;
    const int n0 = blockIdx.y * TN;
    const int tid = threadIdx.x;
    const int w = tid >> 5, lane = tid & 31;
    const int mw = (w & 3) * 32, nw = (w >> 2) * 32;

    __shared__ int spos[TM];
    if (MODE == 0 && tid < TM) spos[tid] = g_pos[t0 + tid];

    float acc[2][4][4];
#pragma unroll
    for (int i = 0; i < 2; i++)
#pragma unroll
        for (int j = 0; j < 4; j++)
#pragma unroll
            for (int q = 0; q < 4; q++) acc[i][j][q] = 0.f;

    const uint4* Bh4 = (const uint4*)Bh_g;
    const uint4* Bl4 = (const uint4*)Bl_g;

#pragma unroll 1
    for (int kc = 0; kc < NCH; kc++) {
        __syncthreads();   // previous chunk's frags consumed
        // ---- A: 128 rows x 64 k fp32 -> bf16 hi/lo ----
        {
            const float* ap;
            int k0a;
            if (MODE == 2) {
                ap = (kc < 4) ? (const float*)g_h : (const float*)g_qcat;
                k0a = (kc & 3) * 64;
            } else {
                ap = asrc;
                k0a = kc * 64;
            }
#pragma unroll
            for (int i = 0; i < 4; i++) {
                int u = i * 512 + tid;
                int row = u >> 4, f4 = u & 15;
                int t = t0 + row;
                float4 x = *(const float4*)(ap + (size_t)t * CD + k0a + f4 * 4);
                if (MODE == 0) {
                    float4 p4 = *(const float4*)(pt + (size_t)(spos[row] + shift) * CD + k0a + f4 * 4);
                    x.x += p4.x; x.y += p4.y; x.z += p4.z; x.w += p4.w;
                    if (saveq) *(float4*)(g_qcat + (size_t)t * CD + k0a + f4 * 4) = x;
                }
                __nv_bfloat162 h01 = __float22bfloat162_rn(make_float2(x.x, x.y));
                __nv_bfloat162 h23 = __float22bfloat162_rn(make_float2(x.z, x.w));
                float2 f01 = __bfloat1622float2(h01);
                float2 f23 = __bfloat1622float2(h23);
                __nv_bfloat162 l01 = __float22bfloat162_rn(make_float2(x.x - f01.x, x.y - f01.y));
                __nv_bfloat162 l23 = __float22bfloat162_rn(make_float2(x.z - f23.x, x.w - f23.y));
                uint32_t off = swz((uint32_t)(row * 128 + f4 * 8));
                *(uint2*)(smc + off) = make_uint2(*(uint32_t*)&h01, *(uint32_t*)&h23);
                *(uint2*)(smc + 16384 + off) = make_uint2(*(uint32_t*)&l01, *(uint32_t*)&l23);
            }
        }
        // ---- B: 128 n-rows x 64 k bf16 (pre-split) ----
        {
#pragma unroll
            for (int i = 0; i < 2; i++) {
                int u = i * 512 + tid;
                int n = u >> 3, kb16 = u & 7;
                size_t gi = (((size_t)(n0 + n) * KW + kc * 64) >> 3) + kb16;
                uint4 vh = Bh4[gi];
                uint4 vl = Bl4[gi];
                uint32_t off = swz((uint32_t)(n * 128 + kb16 * 16));
                *(uint4*)(smc + 32768 + off) = vh;
                *(uint4*)(smc + 49152 + off) = vl;
            }
        }
        __syncthreads();

        // ---- MMA: 4 ksteps of 16 ----
        uint32_t arow = (uint32_t)((mw + (lane & 15)) * 128 + (lane >> 4) * 16);
        uint32_t bn = (uint32_t)((nw + ((lane >> 4) << 3) + (lane & 7)) * 128 +
                                 ((lane >> 3) & 1) * 16);
#pragma unroll
        for (int ks = 0; ks < 4; ks++) {
            uint32_t kb = ks * 32;
            uint32_t ah[2][4], al[2][4], bh[2][4], bl[2][4];
#pragma unroll
            for (int mt = 0; mt < 2; mt++) {
                uint32_t a = su + swz(arow + mt * 16 * 128 + kb);
                ldsm4(ah[mt], a);
                ldsm4(al[mt], a + 16384);
            }
#pragma unroll
            for (int nc = 0; nc < 2; nc++) {
                uint32_t a = su + 32768 + swz(bn + nc * 16 * 128 + kb);
                ldsm4(bh[nc], a);
                ldsm4(bl[nc], a + 16384);
            }
#pragma unroll
            for (int mt = 0; mt < 2; mt++)
#pragma unroll
                for (int nc = 0; nc < 2; nc++) {
                    mma_bf16(acc[mt][nc * 2 + 0], ah[mt], bh[nc][0], bh[nc][1]);
                    mma_bf16(acc[mt][nc * 2 + 1], ah[mt], bh[nc][2], bh[nc][3]);
                    mma_bf16(acc[mt][nc * 2 + 0], al[mt], bh[nc][0], bh[nc][1]);
                    mma_bf16(acc[mt][nc * 2 + 1], al[mt], bh[nc][2], bh[nc][3]);
                    mma_bf16(acc[mt][nc * 2 + 0], ah[mt], bl[nc][0], bl[nc][1]);
                    mma_bf16(acc[mt][nc * 2 + 1], ah[mt], bl[nc][2], bl[nc][3]);
                }
        }
    }

    // ---- epilogue: direct STG.64 per (mt, nt, half) ----
    const float r2 = 0.70710678118654752440f;
#pragma unroll
    for (int mt = 0; mt < 2; mt++) {
#pragma unroll
        for (int nt = 0; nt < 4; nt++) {
            int row = t0 + mw + mt * 16 + (lane >> 2);
            int col = n0 + nw + nt * 8 + (lane & 3) * 2;
            float2 d0 = make_float2(acc[mt][nt][0], acc[mt][nt][1]);
            float2 d1 = make_float2(acc[mt][nt][2], acc[mt][nt][3]);
            if (MODE != 1) {
                float2 b2 = *(const float2*)(bias + col);
                d0.x += b2.x; d0.y += b2.y;
                d1.x += b2.x; d1.y += b2.y;
                if (MODE == 2) {
                    d0.x = 0.5f * d0.x * (1.f + erff(d0.x * r2));
                    d0.y = 0.5f * d0.y * (1.f + erff(d0.y * r2));
                    d1.x = 0.5f * d1.x * (1.f + erff(d1.x * r2));
                    d1.y = 0.5f * d1.y * (1.f + erff(d1.y * r2));
                }
            }
            *(float2*)(outp + (size_t)row * CD + col) = d0;
            *(float2*)(outp + (size_t)(row + 8) * CD + col) = d1;
        }
    }
}

// ---------------------------------------------------------------------------
// LN epilogue: g_h = LayerNorm(tmp + bo + qcat). Warp per row.
// ---------------------------------------------------------------------------
__global__ __launch_bounds__(256) void k_ln(
    const float* __restrict__ bo, const float* __restrict__ lng,
    const float* __restrict__ lnb) {
    int w = threadIdx.x >> 5, lane = threadIdx.x & 31;
    int r = blockIdx.x * 8 + w;
    int c0 = lane * 8;
    float4 t0 = *(const float4*)(g_Q + (size_t)r * CD + c0);
    float4 t1 = *(const float4*)(g_Q + (size_t)r * CD + c0 + 4);
    float4 q0 = *(const float4*)(g_qcat + (size_t)r * CD + c0);
    float4 q1 = *(const float4*)(g_qcat + (size_t)r * CD + c0 + 4);
    float4 b0 = *(const float4*)(bo + c0);
    float4 b1 = *(const float4*)(bo + c0 + 4);
    float v[8];
    v[0] = t0.x + q0.x + b0.x; v[1] = t0.y + q0.y + b0.y;
    v[2] = t0.z + q0.z + b0.z; v[3] = t0.w + q0.w + b0.w;
    v[4] = t1.x + q1.x + b1.x; v[5] = t1.y + q1.y + b1.y;
    v[6] = t1.z + q1.z + b1.z; v[7] = t1.w + q1.w + b1.w;
    float s1 = 0.f, s2 = 0.f;
#pragma unroll
    for (int i = 0; i < 8; i++) { s1 += v[i]; s2 += v[i] * v[i]; }
#pragma unroll
    for (int o = 16; o; o >>= 1) {
        s1 += __shfl_xor_sync(0xffffffffu, s1, o);
        s2 += __shfl_xor_sync(0xffffffffu, s2, o);
    }
    float mu = s1 * (1.f / CD);
    float rs = rsqrtf(s2 * (1.f / CD) - mu * mu + 1e-12f);
    float4 g0 = *(const float4*)(lng + c0);
    float4 g1 = *(const float4*)(lng + c0 + 4);
    float4 bb0 = *(const float4*)(lnb + c0);
    float4 bb1 = *(const float4*)(lnb + c0 + 4);
    float4 o0 = make_float4((v[0] - mu) * rs * g0.x + bb0.x, (v[1] - mu) * rs * g0.y + bb0.y,
                            (v[2] - mu) * rs * g0.z + bb0.z, (v[3] - mu) * rs * g0.w + bb0.w);
    float4 o1 = make_float4((v[4] - mu) * rs * g1.x + bb1.x, (v[5] - mu) * rs * g1.y + bb1.y,
                            (v[6] - mu) * rs * g1.z + bb1.z, (v[7] - mu) * rs * g1.w + bb1.w);
    *(float4*)(g_h + (size_t)r * CD + c0) = o0;
    *(float4*)(g_h + (size_t)r * CD + c0 + 4) = o1;
}

// ---------------------------------------------------------------------------
// Attention (proven R2 form + longest-first order)
// ---------------------------------------------------------------------------
__global__ __launch_bounds__(256, 1) void k_attn(const int* __restrict__ sl) {
    extern __shared__ float sm[];
    float4* Ks   = (float4*)sm;
    float4* Vs   = Ks + 256 * 16;
    float*  prob = (float*)(Vs + 256 * 16);
    float*  qb   = prob + 8 * 4 * 256;

    int b = g_order[blockIdx.x], h = blockIdx.y;
    int L = sl[b], start = g_starts[b];
    int tid = threadIdx.x;
    int hoff = h * CHD;

    for (int qd = tid; qd < L * 16; qd += 256) {
        int j = qd >> 4, d4 = qd & 15;
        int sw = (j << 4) | (d4 ^ (j & 7));
        Ks[sw] = *(const float4*)&g_K[(size_t)(start + j) * CD + hoff + (d4 << 2)];
        Vs[sw] = *(const float4*)&g_V[(size_t)(start + j) * CD + hoff + (d4 << 2)];
    }
    __syncthreads();

    int w = tid >> 5, lane = tid & 31;
    float* pw = prob + w * 1024;
    float* qw = qb + w * 256;
    int lsw = lane & 7;

    for (int q0 = w * 4; q0 < L; q0 += 32) {
        int nq = min(4, L - q0);
#pragma unroll
        for (int qi = 0; qi < 4; qi++) {
            if (qi < nq) {
                const float* qp = &g_Q[(size_t)(start + q0 + qi) * CD + hoff];
                qw[qi * 64 + lane] = qp[lane];
                qw[qi * 64 + 32 + lane] = qp[32 + lane];
            }
        }
        __syncwarp();

        int jrow[8];
#pragma unroll
        for (int jj = 0; jj < 8; jj++) {
            int j = lane + 32 * jj;
            jrow[jj] = (j < L ? j : 0) << 4;
        }
        float s[4][8];
#pragma unroll
        for (int qi = 0; qi < 4; qi++)
#pragma unroll
            for (int jj = 0; jj < 8; jj++) s[qi][jj] = 0.f;
#pragma unroll 4
        for (int d4 = 0; d4 < 16; d4++) {
            float4 kf[8];
            int swd = d4 ^ lsw;
#pragma unroll
            for (int jj = 0; jj < 8; jj++) kf[jj] = Ks[jrow[jj] + swd];
#pragma unroll
            for (int qi = 0; qi < 4; qi++) {
                float4 qv = *(float4*)&qw[qi * 64 + (d4 << 2)];
#pragma unroll
                for (int jj = 0; jj < 8; jj++) {
                    s[qi][jj] = fmaf(qv.x, kf[jj].x, s[qi][jj]);
                    s[qi][jj] = fmaf(qv.y, kf[jj].y, s[qi][jj]);
                    s[qi][jj] = fmaf(qv.z, kf[jj].z, s[qi][jj]);
                    s[qi][jj] = fmaf(qv.w, kf[jj].w, s[qi][jj]);
                }
            }
        }

        float inv[4];
#pragma unroll
        for (int qi = 0; qi < 4; qi++) {
            if (qi >= nq) continue;
            float m = 0.f;
#pragma unroll
            for (int jj = 0; jj < 8; jj++) {
                int j = lane + 32 * jj;
                s[qi][jj] = (j < L) ? s[qi][jj] * 0.125f : -1e30f;
                m = fmaxf(m, s[qi][jj]);
            }
#pragma unroll
            for (int o = 16; o; o >>= 1) m = fmaxf(m, __shfl_xor_sync(0xffffffffu, m, o));
            float ds = (lane == 0) ? __expf(0.f - m) : 0.f;
#pragma unroll
            for (int jj = 0; jj < 8; jj++) {
                int j = lane + 32 * jj;
                if (j < L) {
                    float p = __expf(s[qi][jj] - m);
                    pw[qi * 256 + j] = p;
                    ds += p;
                }
            }
#pragma unroll
            for (int o = 16; o; o >>= 1) ds += __shfl_xor_sync(0xffffffffu, ds, o);
            inv[qi] = 1.f / ds;
        }
        __syncwarp();

        int d4c = lane & 15, par = lane >> 4;
        float4 cacc[4];
#pragma unroll
        for (int qi = 0; qi < 4; qi++) cacc[qi] = make_float4(0.f, 0.f, 0.f, 0.f);
        for (int j = par; j < L; j += 2) {
            float4 vv = Vs[(j << 4) + (d4c ^ (j & 7))];
#pragma unroll
            for (int qi = 0; qi < 4; qi++) {
                float p = pw[qi * 256 + j];
                cacc[qi].x = fmaf(p, vv.x, cacc[qi].x);
                cacc[qi].y = fmaf(p, vv.y, cacc[qi].y);
                cacc[qi].z = fmaf(p, vv.z, cacc[qi].z);
                cacc[qi].w = fmaf(p, vv.w, cacc[qi].w);
            }
        }
#pragma unroll
        for (int qi = 0; qi < 4; qi++) {
            cacc[qi].x += __shfl_xor_sync(0xffffffffu, cacc[qi].x, 16);
            cacc[qi].y += __shfl_xor_sync(0xffffffffu, cacc[qi].y, 16);
            cacc[qi].z += __shfl_xor_sync(0xffffffffu, cacc[qi].z, 16);
            cacc[qi].w += __shfl_xor_sync(0xffffffffu, cacc[qi].w, 16);
            if (qi < nq && par == 0) {
                float4 o = make_float4(cacc[qi].x * inv[qi], cacc[qi].y * inv[qi],
                                       cacc[qi].z * inv[qi], cacc[qi].w * inv[qi]);
                *(float4*)&g_ctx[(size_t)(start + q0 + qi) * CD + hoff + (d4c << 2)] = o;
            }
        }
        __syncwarp();
    }
}

// ---------------------------------------------------------------------------
extern "C" void kernel_launch(void* const* d_in, const int* in_sizes, int n_in,
                              void* d_out, int out_size) {
    const float* qe  = (const float*)d_in[0];
    const float* ke  = (const float*)d_in[1];
    const float* ve  = (const float*)d_in[2];
    const float* pt  = (const float*)d_in[3];
    const float* wq  = (const float*)d_in[4];
    const float* bq  = (const float*)d_in[5];
    const float* wk  = (const float*)d_in[6];
    const float* bk  = (const float*)d_in[7];
    const float* wv  = (const float*)d_in[8];
    const float* bv  = (const float*)d_in[9];
    const float* wo  = (const float*)d_in[10];
    const float* bo  = (const float*)d_in[11];
    const float* lng = (const float*)d_in[12];
    const float* lnb = (const float*)d_in[13];
    const float* wm  = (const float*)d_in[14];
    const float* bm  = (const float*)d_in[15];
    const int*   sl  = (const int*)d_in[16];
    float* out = (float*)d_out;

    float *gQ, *gK, *gV, *gH, *gCtx;
    cudaGetSymbolAddress((void**)&gQ, g_Q);
    cudaGetSymbolAddress((void**)&gK, g_K);
    cudaGetSymbolAddress((void**)&gV, g_V);
    cudaGetSymbolAddress((void**)&gH, g_h);
    cudaGetSymbolAddress((void**)&gCtx, g_ctx);
    __nv_bfloat16 *wqh, *wql, *wkh, *wkl, *wvh, *wvl, *woh, *wol, *wmh, *wml;
    cudaGetSymbolAddress((void**)&wqh, g_wtq_h); cudaGetSymbolAddress((void**)&wql, g_wtq_l);
    cudaGetSymbolAddress((void**)&wkh, g_wtk_h); cudaGetSymbolAddress((void**)&wkl, g_wtk_l);
    cudaGetSymbolAddress((void**)&wvh, g_wtv_h); cudaGetSymbolAddress((void**)&wvl, g_wtv_l);
    cudaGetSymbolAddress((void**)&woh, g_wto_h); cudaGetSymbolAddress((void**)&wol, g_wto_l);
    cudaGetSymbolAddress((void**)&wmh, g_wtm_h); cudaGetSymbolAddress((void**)&wml, g_wtm_l);

    constexpr int SMEM = 65536;
    cudaFuncSetAttribute(k_gemm<0>, cudaFuncAttributeMaxDynamicSharedMemorySize, SMEM);
    cudaFuncSetAttribute(k_gemm<1>, cudaFuncAttributeMaxDynamicSharedMemorySize, SMEM);
    cudaFuncSetAttribute(k_gemm<2>, cudaFuncAttributeMaxDynamicSharedMemorySize, SMEM);

    k_index<<<1, CB>>>(sl);
    k_wt<<<dim3(16, 8, 5), dim3(32, 8)>>>(wq, wk, wv, wo, wm);

    dim3 gg(GBX, 2);
    k_gemm<0><<<gg, 512, SMEM>>>(qe, pt, wqh, wql, bq, gQ, 1, 1);
    k_gemm<0><<<gg, 512, SMEM>>>(ke, pt, wkh, wkl, bk, gK, 0, 0);
    k_gemm<0><<<gg, 512, SMEM>>>(ve, pt, wvh, wvl, bv, gV, 0, 0);

    constexpr size_t ASM = (size_t)(16384 + 16384 + 8192 + 2048) * sizeof(float);
    cudaFuncSetAttribute(k_attn, cudaFuncAttributeMaxDynamicSharedMemorySize, (int)ASM);
    k_attn<<<dim3(CB, CH), 256, ASM>>>(sl);

    k_gemm<1><<<gg, 512, SMEM>>>(gCtx, nullptr, woh, wol, nullptr, gQ, 0, 0);
    k_ln<<<CL1 / 8, 256>>>(bo, lng, lnb);
    k_gemm<2><<<gg, 512, SMEM>>>(nullptr, nullptr, wmh, wml, bm, out, 0, 0);
}

// round 6
// speedup vs baseline: 2.4038x; 1.5775x over previous
#include <cuda_runtime.h>
#include <cuda_bf16.h>
#include <math.h>
#include <stdint.h>

#define CL1 32896
#define CB  256
#define CD  256
#define CH  4
#define CHD 64
#define TM  128
#define TN  128
#define GBX 257     // CL1 / TM

__device__ int   g_starts[CB];
__device__ int   g_pos[CL1];
__device__ int   g_order[CB];
__device__ float g_qcat[CL1 * CD];
__device__ float g_Q[CL1 * CD];      // also selfout GEMM tmp
__device__ float g_K[CL1 * CD];
__device__ float g_V[CL1 * CD];
__device__ float g_ctx[CL1 * CD];
__device__ float g_h[CL1 * CD];
__device__ __nv_bfloat16 g_wtq_h[CD * CD], g_wtq_l[CD * CD];
__device__ __nv_bfloat16 g_wtk_h[CD * CD], g_wtk_l[CD * CD];
__device__ __nv_bfloat16 g_wtv_h[CD * CD], g_wtv_l[CD * CD];
__device__ __nv_bfloat16 g_wto_h[CD * CD], g_wto_l[CD * CD];
__device__ __nv_bfloat16 g_wtm_h[2 * CD * CD], g_wtm_l[2 * CD * CD];

__device__ __forceinline__ uint32_t smem_u32(const void* p) {
    return (uint32_t)__cvta_generic_to_shared(p);
}
__device__ __forceinline__ uint32_t swz(uint32_t off) {
    return off ^ ((off >> 3) & 0x70);
}
__device__ __forceinline__ void ldsm4(uint32_t r[4], uint32_t addr) {
    asm volatile("ldmatrix.sync.aligned.m8n8.x4.shared.b16 {%0,%1,%2,%3}, [%4];"
                 : "=r"(r[0]), "=r"(r[1]), "=r"(r[2]), "=r"(r[3]) : "r"(addr));
}
__device__ __forceinline__ void mma_bf16(float d[4], const uint32_t a[4],
                                         uint32_t b0, uint32_t b1) {
    asm volatile("mma.sync.aligned.m16n8k16.row.col.f32.bf16.bf16.f32 "
                 "{%0,%1,%2,%3}, {%4,%5,%6,%7}, {%8,%9}, {%0,%1,%2,%3};"
                 : "+f"(d[0]), "+f"(d[1]), "+f"(d[2]), "+f"(d[3])
                 : "r"(a[0]), "r"(a[1]), "r"(a[2]), "r"(a[3]), "r"(b0), "r"(b1));
}
__device__ __forceinline__ void split_pack(float a, float b, uint32_t& h, uint32_t& l) {
    __nv_bfloat16 ha = __float2bfloat16_rn(a), hb = __float2bfloat16_rn(b);
    __nv_bfloat162 H = __halves2bfloat162(ha, hb);
    h = *(uint32_t*)&H;
    __nv_bfloat162 Lo = __float22bfloat162_rn(
        make_float2(a - __bfloat162float(ha), b - __bfloat162float(hb)));
    l = *(uint32_t*)&Lo;
}
__device__ __forceinline__ float q2max(float v) {
    v = fmaxf(v, __shfl_xor_sync(0xffffffffu, v, 1));
    return fmaxf(v, __shfl_xor_sync(0xffffffffu, v, 2));
}
__device__ __forceinline__ float q2sum(float v) {
    v += __shfl_xor_sync(0xffffffffu, v, 1);
    return v + __shfl_xor_sync(0xffffffffu, v, 2);
}

// ---------------------------------------------------------------------------
__global__ void k_index(const int* __restrict__ sl) {
    __shared__ int st[CB];
    int tid = threadIdx.x;
    if (tid == 0) {
        int a = 0;
        for (int b = 0; b < CB; b++) { st[b] = a; a += sl[b]; }
    }
    __syncthreads();
    int s = st[tid], len = sl[tid];
    g_starts[tid] = s;
    g_order[CB - len] = tid;
    for (int i = 0; i < len; i++) g_pos[s + i] = i;
}

__global__ void k_wt(const float* __restrict__ wq, const float* __restrict__ wk,
                     const float* __restrict__ wv, const float* __restrict__ wo,
                     const float* __restrict__ wm) {
    __shared__ float t[32][33];
    int z = blockIdx.z;
    const float* W; __nv_bfloat16* oh; __nv_bfloat16* ol; int K;
    switch (z) {
        case 0: W = wq; oh = g_wtq_h; ol = g_wtq_l; K = 256; break;
        case 1: W = wk; oh = g_wtk_h; ol = g_wtk_l; K = 256; break;
        case 2: W = wv; oh = g_wtv_h; ol = g_wtv_l; K = 256; break;
        case 3: W = wo; oh = g_wto_h; ol = g_wto_l; K = 256; break;
        default: W = wm; oh = g_wtm_h; ol = g_wtm_l; K = 512; break;
    }
    int k0 = blockIdx.x * 32, n0 = blockIdx.y * 32;
    if (k0 >= K) return;
    int tx = threadIdx.x, ty = threadIdx.y;
#pragma unroll
    for (int i = 0; i < 4; i++)
        t[ty + 8 * i][tx] = W[(size_t)(k0 + ty + 8 * i) * CD + n0 + tx];
    __syncthreads();
#pragma unroll
    for (int i = 0; i < 4; i++) {
        int rr = ty + 8 * i;
        float v = t[tx][rr];
        __nv_bfloat16 h = __float2bfloat16_rn(v);
        oh[(size_t)(n0 + rr) * K + k0 + tx] = h;
        ol[(size_t)(n0 + rr) * K + k0 + tx] = __float2bfloat16_rn(v - __bfloat162float(h));
    }
}

// ---------------------------------------------------------------------------
// Double-buffered mma.sync bf16-split GEMM. 512 thr, tile 128x128, K chunks 64.
// ---------------------------------------------------------------------------
#define STG 65536   // per-stage bytes: Ah 16K | Al 16K | Bh 16K | Bl 16K
#define SMEM_G (2 * STG)

template <int MODE>
__global__ __launch_bounds__(512, 1)
void k_gemm(const float* __restrict__ asrc, const float* __restrict__ pt,
            const __nv_bfloat16* __restrict__ Bh_g, const __nv_bfloat16* __restrict__ Bl_g,
            const float* __restrict__ bias, float* __restrict__ outp,
            int shift, int saveq) {
    extern __shared__ char smc[];
    const uint32_t su = smem_u32(smc);
    constexpr int KW = (MODE == 2) ? 512 : 256;
    constexpr int NCH = KW / 64;
    const int t0 = blockIdx.x * TM;
    const int n0 = blockIdx.y * TN;
    const int tid = threadIdx.x;
    const int w = tid >> 5, lane = tid & 31;
    const int mw = (w & 3) * 32, nw = (w >> 2) * 32;

    __shared__ int spos[TM];
    if (MODE == 0 && tid < TM) spos[tid] = g_pos[t0 + tid];
    if (MODE == 0) __syncthreads();

    float acc[2][4][4];
#pragma unroll
    for (int i = 0; i < 2; i++)
#pragma unroll
        for (int j = 0; j < 4; j++)
#pragma unroll
            for (int q = 0; q < 4; q++) acc[i][j][q] = 0.f;

    const uint4* Bh4 = (const uint4*)Bh_g;
    const uint4* Bl4 = (const uint4*)Bl_g;

    float4 aR[4];
    uint4 bhR[2], blR[2];

    auto ldA = [&](int kc) {
        const float* ap;
        int k0a;
        if (MODE == 2) {
            ap = (kc < 4) ? (const float*)g_h : (const float*)g_qcat;
            k0a = (kc & 3) * 64;
        } else { ap = asrc; k0a = kc * 64; }
#pragma unroll
        for (int i = 0; i < 4; i++) {
            int u = i * 512 + tid;
            int row = u >> 4, f4 = u & 15;
            int t = t0 + row;
            float4 x = *(const float4*)(ap + (size_t)t * CD + k0a + f4 * 4);
            if (MODE == 0) {
                float4 p4 = *(const float4*)(pt + (size_t)(spos[row] + shift) * CD + k0a + f4 * 4);
                x.x += p4.x; x.y += p4.y; x.z += p4.z; x.w += p4.w;
                if (saveq) *(float4*)(g_qcat + (size_t)t * CD + k0a + f4 * 4) = x;
            }
            aR[i] = x;
        }
    };
    auto ldB = [&](int kc) {
#pragma unroll
        for (int i = 0; i < 2; i++) {
            int u = i * 512 + tid;
            int n = u >> 3, kb16 = u & 7;
            size_t gi = (((size_t)(n0 + n) * KW + kc * 64) >> 3) + kb16;
            bhR[i] = Bh4[gi];
            blR[i] = Bl4[gi];
        }
    };
    auto sts = [&](int s) {
        char* sb = smc + s * STG;
#pragma unroll
        for (int i = 0; i < 4; i++) {
            int u = i * 512 + tid;
            int row = u >> 4, f4 = u & 15;
            float4 x = aR[i];
            uint32_t h01, l01, h23, l23;
            split_pack(x.x, x.y, h01, l01);
            split_pack(x.z, x.w, h23, l23);
            uint32_t off = swz((uint32_t)(row * 128 + f4 * 8));
            *(uint2*)(sb + off) = make_uint2(h01, h23);
            *(uint2*)(sb + 16384 + off) = make_uint2(l01, l23);
        }
#pragma unroll
        for (int i = 0; i < 2; i++) {
            int u = i * 512 + tid;
            int n = u >> 3, kb16 = u & 7;
            uint32_t off = swz((uint32_t)(n * 128 + kb16 * 16));
            *(uint4*)(sb + 32768 + off) = bhR[i];
            *(uint4*)(sb + 49152 + off) = blR[i];
        }
    };

    ldA(0); ldB(0);
#pragma unroll 1
    for (int kc = 0; kc < NCH; kc++) {
        int s = kc & 1;
        sts(s);
        if (kc + 1 < NCH) { ldA(kc + 1); ldB(kc + 1); }
        __syncthreads();
        const uint32_t sb = su + s * STG;
        uint32_t arow = (uint32_t)((mw + (lane & 15)) * 128 + (lane >> 4) * 16);
        uint32_t bn = (uint32_t)((nw + ((lane >> 4) << 3) + (lane & 7)) * 128 +
                                 ((lane >> 3) & 1) * 16);
#pragma unroll
        for (int ks = 0; ks < 4; ks++) {
            uint32_t kb = ks * 32;
            uint32_t ah[2][4], al[2][4], bh[2][4], bl[2][4];
#pragma unroll
            for (int mt = 0; mt < 2; mt++) {
                uint32_t a = sb + swz(arow + mt * 16 * 128 + kb);
                ldsm4(ah[mt], a);
                ldsm4(al[mt], a + 16384);
            }
#pragma unroll
            for (int nc = 0; nc < 2; nc++) {
                uint32_t a = sb + 32768 + swz(bn + nc * 16 * 128 + kb);
                ldsm4(bh[nc], a);
                ldsm4(bl[nc], a + 16384);
            }
#pragma unroll
            for (int mt = 0; mt < 2; mt++)
#pragma unroll
                for (int nc = 0; nc < 2; nc++) {
                    mma_bf16(acc[mt][nc * 2 + 0], ah[mt], bh[nc][0], bh[nc][1]);
                    mma_bf16(acc[mt][nc * 2 + 1], ah[mt], bh[nc][2], bh[nc][3]);
                    mma_bf16(acc[mt][nc * 2 + 0], al[mt], bh[nc][0], bh[nc][1]);
                    mma_bf16(acc[mt][nc * 2 + 1], al[mt], bh[nc][2], bh[nc][3]);
                    mma_bf16(acc[mt][nc * 2 + 0], ah[mt], bl[nc][0], bl[nc][1]);
                    mma_bf16(acc[mt][nc * 2 + 1], ah[mt], bl[nc][2], bl[nc][3]);
                }
        }
    }

    const float r2 = 0.70710678118654752440f;
#pragma unroll
    for (int mt = 0; mt < 2; mt++) {
#pragma unroll
        for (int nt = 0; nt < 4; nt++) {
            int row = t0 + mw + mt * 16 + (lane >> 2);
            int col = n0 + nw + nt * 8 + (lane & 3) * 2;
            float2 d0 = make_float2(acc[mt][nt][0], acc[mt][nt][1]);
            float2 d1 = make_float2(acc[mt][nt][2], acc[mt][nt][3]);
            if (MODE != 1) {
                float2 b2 = *(const float2*)(bias + col);
                d0.x += b2.x; d0.y += b2.y;
                d1.x += b2.x; d1.y += b2.y;
                if (MODE == 2) {
                    d0.x = 0.5f * d0.x * (1.f + erff(d0.x * r2));
                    d0.y = 0.5f * d0.y * (1.f + erff(d0.y * r2));
                    d1.x = 0.5f * d1.x * (1.f + erff(d1.x * r2));
                    d1.y = 0.5f * d1.y * (1.f + erff(d1.y * r2));
                }
            }
            *(float2*)(outp + (size_t)row * CD + col) = d0;
            *(float2*)(outp + (size_t)(row + 8) * CD + col) = d1;
        }
    }
}

// ---------------------------------------------------------------------------
// LN epilogue: g_h = LayerNorm(g_Q(tmp) + bo + qcat). Warp per row.
// ---------------------------------------------------------------------------
__global__ __launch_bounds__(256) void k_ln(
    const float* __restrict__ bo, const float* __restrict__ lng,
    const float* __restrict__ lnb) {
    int w = threadIdx.x >> 5, lane = threadIdx.x & 31;
    int r = blockIdx.x * 8 + w;
    int c0 = lane * 8;
    float4 t0 = *(const float4*)(g_Q + (size_t)r * CD + c0);
    float4 t1 = *(const float4*)(g_Q + (size_t)r * CD + c0 + 4);
    float4 q0 = *(const float4*)(g_qcat + (size_t)r * CD + c0);
    float4 q1 = *(const float4*)(g_qcat + (size_t)r * CD + c0 + 4);
    float4 b0 = *(const float4*)(bo + c0);
    float4 b1 = *(const float4*)(bo + c0 + 4);
    float v[8];
    v[0] = t0.x + q0.x + b0.x; v[1] = t0.y + q0.y + b0.y;
    v[2] = t0.z + q0.z + b0.z; v[3] = t0.w + q0.w + b0.w;
    v[4] = t1.x + q1.x + b1.x; v[5] = t1.y + q1.y + b1.y;
    v[6] = t1.z + q1.z + b1.z; v[7] = t1.w + q1.w + b1.w;
    float s1 = 0.f, s2 = 0.f;
#pragma unroll
    for (int i = 0; i < 8; i++) { s1 += v[i]; s2 += v[i] * v[i]; }
#pragma unroll
    for (int o = 16; o; o >>= 1) {
        s1 += __shfl_xor_sync(0xffffffffu, s1, o);
        s2 += __shfl_xor_sync(0xffffffffu, s2, o);
    }
    float mu = s1 * (1.f / CD);
    float rs = rsqrtf(s2 * (1.f / CD) - mu * mu + 1e-12f);
    float4 g0 = *(const float4*)(lng + c0);
    float4 g1 = *(const float4*)(lng + c0 + 4);
    float4 bb0 = *(const float4*)(lnb + c0);
    float4 bb1 = *(const float4*)(lnb + c0 + 4);
    float4 o0 = make_float4((v[0] - mu) * rs * g0.x + bb0.x, (v[1] - mu) * rs * g0.y + bb0.y,
                            (v[2] - mu) * rs * g0.z + bb0.z, (v[3] - mu) * rs * g0.w + bb0.w);
    float4 o1 = make_float4((v[4] - mu) * rs * g1.x + bb1.x, (v[5] - mu) * rs * g1.y + bb1.y,
                            (v[6] - mu) * rs * g1.z + bb1.z, (v[7] - mu) * rs * g1.w + bb1.w);
    *(float4*)(g_h + (size_t)r * CD + c0) = o0;
    *(float4*)(g_h + (size_t)r * CD + c0 + 4) = o1;
}

// ---------------------------------------------------------------------------
// Flash-style mma attention. CTA = (b,h), 256 thr = 8 warps x 32 query rows.
// Q pre-scaled by 1/8, bf16 hi/lo; K bf16 hi/lo; V bf16 transposed per chunk.
// Zero-slot: init m=0, l=1.
// ---------------------------------------------------------------------------
#define QH_OFF 0
#define QL_OFF 32768
#define KH_OFF 65536
#define KL_OFF 98304
#define VT_OFF 131072
#define ATT_SMEM 163840

__global__ __launch_bounds__(256, 1) void k_attn(const int* __restrict__ sl) {
    extern __shared__ char smc[];
    const uint32_t su = smem_u32(smc);
    int b = g_order[blockIdx.x], h = blockIdx.y;
    int L = sl[b], start = g_starts[b], hoff = h * CHD;
    int tid = threadIdx.x;

    // ---- stage Q (scaled) and K, split hi/lo ----
#pragma unroll 1
    for (int u = tid; u < 2048; u += 256) {
        int arr = u >> 10;                 // 0 = Q, 1 = K
        int row = (u >> 2) & 255, seg = u & 3;
        const float* gp = (arr == 0 ? g_Q : g_K) + (size_t)(start + row) * CD + hoff + seg * 16;
        float sc = (arr == 0) ? 0.125f : 1.0f;
        bool vld = row < L;
        uint32_t hi[8], lo[8];
#pragma unroll
        for (int i = 0; i < 4; i++) {
            float4 x = vld ? *(const float4*)(gp + i * 4) : make_float4(0, 0, 0, 0);
            split_pack(x.x * sc, x.y * sc, hi[2 * i], lo[2 * i]);
            split_pack(x.z * sc, x.w * sc, hi[2 * i + 1], lo[2 * i + 1]);
        }
        uint32_t base = (arr == 0) ? QH_OFF : KH_OFF;
        uint32_t o0 = swz((uint32_t)(row * 128 + seg * 32));
        uint32_t o1 = swz((uint32_t)(row * 128 + seg * 32 + 16));
        *(uint4*)(smc + base + o0) = make_uint4(hi[0], hi[1], hi[2], hi[3]);
        *(uint4*)(smc + base + o1) = make_uint4(hi[4], hi[5], hi[6], hi[7]);
        *(uint4*)(smc + base + 32768 + o0) = make_uint4(lo[0], lo[1], lo[2], lo[3]);
        *(uint4*)(smc + base + 32768 + o1) = make_uint4(lo[4], lo[5], lo[6], lo[7]);
    }
    // ---- stage V transposed: Vt[chunk][dim][key] bf16 ----
#pragma unroll 1
    for (int u = tid; u < 1024; u += 256) {
        int row = u >> 2, seg = u & 3;
        const float* gp = g_V + (size_t)(start + row) * CD + hoff + seg * 16;
        bool vld = row < L;
        uint32_t cb = VT_OFF + (row >> 6) * 8192;
        int kin2 = (row & 63) * 2;
#pragma unroll
        for (int i = 0; i < 4; i++) {
            float4 x = vld ? *(const float4*)(gp + i * 4) : make_float4(0, 0, 0, 0);
            int d0 = seg * 16 + i * 4;
            *(__nv_bfloat16*)(smc + cb + swz((uint32_t)((d0 + 0) * 128 + kin2))) = __float2bfloat16_rn(x.x);
            *(__nv_bfloat16*)(smc + cb + swz((uint32_t)((d0 + 1) * 128 + kin2))) = __float2bfloat16_rn(x.y);
            *(__nv_bfloat16*)(smc + cb + swz((uint32_t)((d0 + 2) * 128 + kin2))) = __float2bfloat16_rn(x.z);
            *(__nv_bfloat16*)(smc + cb + swz((uint32_t)((d0 + 3) * 128 + kin2))) = __float2bfloat16_rn(x.w);
        }
    }
    __syncthreads();

    int w = tid >> 5, lane = tid & 31;
    int q0w = w * 32;
    if (q0w >= L) return;

    float O[2][8][4];
#pragma unroll
    for (int mt = 0; mt < 2; mt++)
#pragma unroll
        for (int nt = 0; nt < 8; nt++)
#pragma unroll
            for (int e = 0; e < 4; e++) O[mt][nt][e] = 0.f;
    float m_run[2][2] = {{0.f, 0.f}, {0.f, 0.f}};
    float l_run[2][2] = {{1.f, 1.f}, {1.f, 1.f}};

    int nch = (L + 63) >> 6;
#pragma unroll 1
    for (int c = 0; c < nch; c++) {
        int j0 = c * 64;
        float S[2][8][4];
#pragma unroll
        for (int mt = 0; mt < 2; mt++)
#pragma unroll
            for (int nt = 0; nt < 8; nt++)
#pragma unroll
                for (int e = 0; e < 4; e++) S[mt][nt][e] = 0.f;

        // scores: S = (Q/8) @ K^T, 3-term bf16 split
#pragma unroll
        for (int ks = 0; ks < 4; ks++) {
            uint32_t aH[2][4], aL[2][4];
#pragma unroll
            for (int mt = 0; mt < 2; mt++) {
                uint32_t ao = swz((uint32_t)((q0w + mt * 16 + (lane & 15)) * 128 +
                                             (lane >> 4) * 16 + ks * 32));
                ldsm4(aH[mt], su + QH_OFF + ao);
                ldsm4(aL[mt], su + QL_OFF + ao);
            }
#pragma unroll
            for (int p = 0; p < 4; p++) {
                uint32_t bo_ = swz((uint32_t)((j0 + p * 16 + ((lane >> 4) << 3) + (lane & 7)) * 128 +
                                              ((lane >> 3) & 1) * 16 + ks * 32));
                uint32_t bh[4], bl[4];
                ldsm4(bh, su + KH_OFF + bo_);
                ldsm4(bl, su + KL_OFF + bo_);
#pragma unroll
                for (int mt = 0; mt < 2; mt++) {
                    mma_bf16(S[mt][2 * p], aH[mt], bh[0], bh[1]);
                    mma_bf16(S[mt][2 * p + 1], aH[mt], bh[2], bh[3]);
                    mma_bf16(S[mt][2 * p], aL[mt], bh[0], bh[1]);
                    mma_bf16(S[mt][2 * p + 1], aL[mt], bh[2], bh[3]);
                    mma_bf16(S[mt][2 * p], aH[mt], bl[0], bl[1]);
                    mma_bf16(S[mt][2 * p + 1], aH[mt], bl[2], bl[3]);
                }
            }
        }

        // online softmax (zero-slot already in m_run/l_run init)
        int col01 = j0 + (lane & 3) * 2;
#pragma unroll
        for (int mt = 0; mt < 2; mt++) {
#pragma unroll
            for (int nt = 0; nt < 8; nt++) {
                int base = col01 + nt * 8;
                if (base >= L)     { S[mt][nt][0] = -1e30f; S[mt][nt][2] = -1e30f; }
                if (base + 1 >= L) { S[mt][nt][1] = -1e30f; S[mt][nt][3] = -1e30f; }
            }
            float rmA = -1e30f, rmB = -1e30f;
#pragma unroll
            for (int nt = 0; nt < 8; nt++) {
                rmA = fmaxf(rmA, fmaxf(S[mt][nt][0], S[mt][nt][1]));
                rmB = fmaxf(rmB, fmaxf(S[mt][nt][2], S[mt][nt][3]));
            }
            rmA = q2max(rmA); rmB = q2max(rmB);
            float mA = fmaxf(m_run[mt][0], rmA), mB = fmaxf(m_run[mt][1], rmB);
            float aA = __expf(m_run[mt][0] - mA), aB = __expf(m_run[mt][1] - mB);
            m_run[mt][0] = mA; m_run[mt][1] = mB;
            float sA = 0.f, sB = 0.f;
#pragma unroll
            for (int nt = 0; nt < 8; nt++) {
                S[mt][nt][0] = __expf(S[mt][nt][0] - mA);
                S[mt][nt][1] = __expf(S[mt][nt][1] - mA);
                S[mt][nt][2] = __expf(S[mt][nt][2] - mB);
                S[mt][nt][3] = __expf(S[mt][nt][3] - mB);
                sA += S[mt][nt][0] + S[mt][nt][1];
                sB += S[mt][nt][2] + S[mt][nt][3];
            }
            sA = q2sum(sA); sB = q2sum(sB);
            l_run[mt][0] = l_run[mt][0] * aA + sA;
            l_run[mt][1] = l_run[mt][1] * aB + sB;
#pragma unroll
            for (int nt = 0; nt < 8; nt++) {
                O[mt][nt][0] *= aA; O[mt][nt][1] *= aA;
                O[mt][nt][2] *= aB; O[mt][nt][3] *= aB;
            }
        }

        // PV: ctx += P @ V  (P hi/lo split, V bf16)
#pragma unroll
        for (int pt = 0; pt < 4; pt++) {
            uint32_t vb[4][4];
#pragma unroll
            for (int np = 0; np < 4; np++) {
                uint32_t vo = swz((uint32_t)((np * 16 + ((lane >> 4) << 3) + (lane & 7)) * 128 +
                                             ((lane >> 3) & 1) * 16 + pt * 32));
                ldsm4(vb[np], su + VT_OFF + c * 8192 + vo);
            }
#pragma unroll
            for (int mt = 0; mt < 2; mt++) {
                uint32_t pa[4], pl[4];
                split_pack(S[mt][2 * pt][0], S[mt][2 * pt][1], pa[0], pl[0]);
                split_pack(S[mt][2 * pt][2], S[mt][2 * pt][3], pa[1], pl[1]);
                split_pack(S[mt][2 * pt + 1][0], S[mt][2 * pt + 1][1], pa[2], pl[2]);
                split_pack(S[mt][2 * pt + 1][2], S[mt][2 * pt + 1][3], pa[3], pl[3]);
#pragma unroll
                for (int np = 0; np < 4; np++) {
                    mma_bf16(O[mt][2 * np], pa, vb[np][0], vb[np][1]);
                    mma_bf16(O[mt][2 * np + 1], pa, vb[np][2], vb[np][3]);
                    mma_bf16(O[mt][2 * np], pl, vb[np][0], vb[np][1]);
                    mma_bf16(O[mt][2 * np + 1], pl, vb[np][2], vb[np][3]);
                }
            }
        }
    }

    // ---- store ctx ----
#pragma unroll
    for (int mt = 0; mt < 2; mt++) {
        float iA = 1.f / l_run[mt][0], iB = 1.f / l_run[mt][1];
        int rA = q0w + mt * 16 + (lane >> 2);
        int rB = rA + 8;
#pragma unroll
        for (int nt = 0; nt < 8; nt++) {
            int col = hoff + nt * 8 + (lane & 3) * 2;
            if (rA < L)
                *(float2*)(g_ctx + (size_t)(start + rA) * CD + col) =
                    make_float2(O[mt][nt][0] * iA, O[mt][nt][1] * iA);
            if (rB < L)
                *(float2*)(g_ctx + (size_t)(start + rB) * CD + col) =
                    make_float2(O[mt][nt][2] * iB, O[mt][nt][3] * iB);
        }
    }
}

// ---------------------------------------------------------------------------
extern "C" void kernel_launch(void* const* d_in, const int* in_sizes, int n_in,
                              void* d_out, int out_size) {
    const float* qe  = (const float*)d_in[0];
    const float* ke  = (const float*)d_in[1];
    const float* ve  = (const float*)d_in[2];
    const float* pt  = (const float*)d_in[3];
    const float* wq  = (const float*)d_in[4];
    const float* bq  = (const float*)d_in[5];
    const float* wk  = (const float*)d_in[6];
    const float* bk  = (const float*)d_in[7];
    const float* wv  = (const float*)d_in[8];
    const float* bv  = (const float*)d_in[9];
    const float* wo  = (const float*)d_in[10];
    const float* bo  = (const float*)d_in[11];
    const float* lng = (const float*)d_in[12];
    const float* lnb = (const float*)d_in[13];
    const float* wm  = (const float*)d_in[14];
    const float* bm  = (const float*)d_in[15];
    const int*   sl  = (const int*)d_in[16];
    float* out = (float*)d_out;

    float *gQ, *gK, *gV, *gCtx;
    cudaGetSymbolAddress((void**)&gQ, g_Q);
    cudaGetSymbolAddress((void**)&gK, g_K);
    cudaGetSymbolAddress((void**)&gV, g_V);
    cudaGetSymbolAddress((void**)&gCtx, g_ctx);
    __nv_bfloat16 *wqh, *wql, *wkh, *wkl, *wvh, *wvl, *woh, *wol, *wmh, *wml;
    cudaGetSymbolAddress((void**)&wqh, g_wtq_h); cudaGetSymbolAddress((void**)&wql, g_wtq_l);
    cudaGetSymbolAddress((void**)&wkh, g_wtk_h); cudaGetSymbolAddress((void**)&wkl, g_wtk_l);
    cudaGetSymbolAddress((void**)&wvh, g_wtv_h); cudaGetSymbolAddress((void**)&wvl, g_wtv_l);
    cudaGetSymbolAddress((void**)&woh, g_wto_h); cudaGetSymbolAddress((void**)&wol, g_wto_l);
    cudaGetSymbolAddress((void**)&wmh, g_wtm_h); cudaGetSymbolAddress((void**)&wml, g_wtm_l);

    cudaFuncSetAttribute(k_gemm<0>, cudaFuncAttributeMaxDynamicSharedMemorySize, SMEM_G);
    cudaFuncSetAttribute(k_gemm<1>, cudaFuncAttributeMaxDynamicSharedMemorySize, SMEM_G);
    cudaFuncSetAttribute(k_gemm<2>, cudaFuncAttributeMaxDynamicSharedMemorySize, SMEM_G);
    cudaFuncSetAttribute(k_attn, cudaFuncAttributeMaxDynamicSharedMemorySize, ATT_SMEM);

    k_index<<<1, CB>>>(sl);
    k_wt<<<dim3(16, 8, 5), dim3(32, 8)>>>(wq, wk, wv, wo, wm);

    dim3 gg(GBX, 2);
    k_gemm<0><<<gg, 512, SMEM_G>>>(qe, pt, wqh, wql, bq, gQ, 1, 1);
    k_gemm<0><<<gg, 512, SMEM_G>>>(ke, pt, wkh, wkl, bk, gK, 0, 0);
    k_gemm<0><<<gg, 512, SMEM_G>>>(ve, pt, wvh, wvl, bv, gV, 0, 0);

    k_attn<<<dim3(CB, CH), 256, ATT_SMEM>>>(sl);

    k_gemm<1><<<gg, 512, SMEM_G>>>(gCtx, nullptr, woh, wol, nullptr, gQ, 0, 0);
    k_ln<<<CL1 / 8, 256>>>(bo, lng, lnb);
    k_gemm<2><<<gg, 512, SMEM_G>>>(nullptr, nullptr, wmh, wml, bm, out, 0, 0);
}

// round 7
// speedup vs baseline: 2.4936x; 1.0374x over previous
#include <cuda_runtime.h>
#include <cuda_bf16.h>
#include <math.h>
#include <stdint.h>

#define CL1 32896
#define CB  256
#define CD  256
#define CH  4
#define CHD 64
#define TM  128
#define GBX 257

__device__ int   g_starts[CB];
__device__ int   g_pos[CL1];
__device__ int   g_order[CB];
__device__ float g_qc[CL1 * CD];     // qcat fp32 (LN residual)
__device__ float g_tmp[CL1 * CD];    // selfout GEMM raw out
__device__ __nv_bfloat16 g_Qh[CL1 * CD], g_Ql[CL1 * CD];   // Q/8 split
__device__ __nv_bfloat16 g_Kh[CL1 * CD], g_Kl[CL1 * CD];
__device__ __nv_bfloat16 g_Vb[CL1 * CD];
__device__ __nv_bfloat16 g_qch[CL1 * CD], g_qcl[CL1 * CD];
__device__ __nv_bfloat16 g_ch[CL1 * CD], g_cl[CL1 * CD];   // ctx split
__device__ __nv_bfloat16 g_hh[CL1 * CD], g_hl[CL1 * CD];   // h split
__device__ __nv_bfloat16 g_wtq_h[CD * CD], g_wtq_l[CD * CD];
__device__ __nv_bfloat16 g_wtk_h[CD * CD], g_wtk_l[CD * CD];
__device__ __nv_bfloat16 g_wtv_h[CD * CD], g_wtv_l[CD * CD];
__device__ __nv_bfloat16 g_wto_h[CD * CD], g_wto_l[CD * CD];
__device__ __nv_bfloat16 g_wtm_h[2 * CD * CD], g_wtm_l[2 * CD * CD];

__device__ __forceinline__ uint32_t smem_u32(const void* p) {
    return (uint32_t)__cvta_generic_to_shared(p);
}
__device__ __forceinline__ uint32_t swz(uint32_t off) {
    return off ^ ((off >> 3) & 0x70);
}
__device__ __forceinline__ void ldsm4(uint32_t r[4], uint32_t addr) {
    asm volatile("ldmatrix.sync.aligned.m8n8.x4.shared.b16 {%0,%1,%2,%3}, [%4];"
                 : "=r"(r[0]), "=r"(r[1]), "=r"(r[2]), "=r"(r[3]) : "r"(addr));
}
__device__ __forceinline__ void mma_bf16(float d[4], const uint32_t a[4],
                                         uint32_t b0, uint32_t b1) {
    asm volatile("mma.sync.aligned.m16n8k16.row.col.f32.bf16.bf16.f32 "
                 "{%0,%1,%2,%3}, {%4,%5,%6,%7}, {%8,%9}, {%0,%1,%2,%3};"
                 : "+f"(d[0]), "+f"(d[1]), "+f"(d[2]), "+f"(d[3])
                 : "r"(a[0]), "r"(a[1]), "r"(a[2]), "r"(a[3]), "r"(b0), "r"(b1));
}
__device__ __forceinline__ void split_pack(float a, float b, uint32_t& h, uint32_t& l) {
    __nv_bfloat16 ha = __float2bfloat16_rn(a), hb = __float2bfloat16_rn(b);
    __nv_bfloat162 H = __halves2bfloat162(ha, hb);
    h = *(uint32_t*)&H;
    __nv_bfloat162 Lo = __float22bfloat162_rn(
        make_float2(a - __bfloat162float(ha), b - __bfloat162float(hb)));
    l = *(uint32_t*)&Lo;
}
__device__ __forceinline__ float q2max(float v) {
    v = fmaxf(v, __shfl_xor_sync(0xffffffffu, v, 1));
    return fmaxf(v, __shfl_xor_sync(0xffffffffu, v, 2));
}
__device__ __forceinline__ float q2sum(float v) {
    v += __shfl_xor_sync(0xffffffffu, v, 1);
    return v + __shfl_xor_sync(0xffffffffu, v, 2);
}
__device__ __forceinline__ void cp16(uint32_t dst, const void* src) {
    asm volatile("cp.async.cg.shared.global [%0], [%1], 16;" :: "r"(dst), "l"(src));
}
__device__ __forceinline__ void cp16z(uint32_t dst, const void* src, int do_copy) {
    asm volatile("cp.async.cg.shared.global [%0], [%1], 16, %2;"
                 :: "r"(dst), "l"(src), "r"(do_copy ? 16 : 0));
}
#define CP_COMMIT() asm volatile("cp.async.commit_group;" ::: "memory")
#define CP_WAIT1()  asm volatile("cp.async.wait_group 1;" ::: "memory")
#define CP_WAIT0()  asm volatile("cp.async.wait_group 0;" ::: "memory")

// ---------------------------------------------------------------------------
__global__ void k_index(const int* __restrict__ sl) {
    __shared__ int st[CB];
    int tid = threadIdx.x;
    if (tid == 0) {
        int a = 0;
        for (int b = 0; b < CB; b++) { st[b] = a; a += sl[b]; }
    }
    __syncthreads();
    int s = st[tid], len = sl[tid];
    g_starts[tid] = s;
    g_order[CB - len] = tid;
    for (int i = 0; i < len; i++) g_pos[s + i] = i;
}

__global__ void k_wt(const float* __restrict__ wq, const float* __restrict__ wk,
                     const float* __restrict__ wv, const float* __restrict__ wo,
                     const float* __restrict__ wm) {
    __shared__ float t[32][33];
    int z = blockIdx.z;
    const float* W; __nv_bfloat16* oh; __nv_bfloat16* ol; int K;
    switch (z) {
        case 0: W = wq; oh = g_wtq_h; ol = g_wtq_l; K = 256; break;
        case 1: W = wk; oh = g_wtk_h; ol = g_wtk_l; K = 256; break;
        case 2: W = wv; oh = g_wtv_h; ol = g_wtv_l; K = 256; break;
        case 3: W = wo; oh = g_wto_h; ol = g_wto_l; K = 256; break;
        default: W = wm; oh = g_wtm_h; ol = g_wtm_l; K = 512; break;
    }
    int k0 = blockIdx.x * 32, n0 = blockIdx.y * 32;
    if (k0 >= K) return;
    int tx = threadIdx.x, ty = threadIdx.y;
#pragma unroll
    for (int i = 0; i < 4; i++)
        t[ty + 8 * i][tx] = W[(size_t)(k0 + ty + 8 * i) * CD + n0 + tx];
    __syncthreads();
#pragma unroll
    for (int i = 0; i < 4; i++) {
        int rr = ty + 8 * i;
        float v = t[tx][rr];
        __nv_bfloat16 h = __float2bfloat16_rn(v);
        oh[(size_t)(n0 + rr) * K + k0 + tx] = h;
        ol[(size_t)(n0 + rr) * K + k0 + tx] = __float2bfloat16_rn(v - __bfloat162float(h));
    }
}

// ---------------------------------------------------------------------------
// Stage layout: Ah 16K | Al 16K | Bh 16K | Bl 16K = 64KB
#define STG 65536
#define SMEM_P (2 * STG)
#define SMEM_G3 (3 * STG)

// Projections: z = 0(Q) 1(K) 2(V). fp32 A (emb+pos) register-double-buffered.
__global__ __launch_bounds__(512, 1) void k_proj(
    const float* __restrict__ qe, const float* __restrict__ ke,
    const float* __restrict__ ve, const float* __restrict__ pt,
    const float* __restrict__ bq, const float* __restrict__ bk,
    const float* __restrict__ bv) {
    extern __shared__ char smc[];
    const uint32_t su = smem_u32(smc);
    const int z = blockIdx.z;
    const float* emb = z == 0 ? qe : (z == 1 ? ke : ve);
    const __nv_bfloat16* Bh_g = z == 0 ? g_wtq_h : (z == 1 ? g_wtk_h : g_wtv_h);
    const __nv_bfloat16* Bl_g = z == 0 ? g_wtq_l : (z == 1 ? g_wtk_l : g_wtv_l);
    const float* bias = z == 0 ? bq : (z == 1 ? bk : bv);
    const int shift = (z == 0) ? 1 : 0;
    const bool saveq = (z == 0);
    const int t0 = blockIdx.x * TM, n0 = blockIdx.y * 128;
    const int tid = threadIdx.x, w = tid >> 5, lane = tid & 31;
    const int mw = (w & 3) * 32, nw = (w >> 2) * 32;

    __shared__ int spos[TM];
    if (tid < TM) spos[tid] = g_pos[t0 + tid];
    __syncthreads();

    float acc[2][4][4];
#pragma unroll
    for (int i = 0; i < 2; i++)
#pragma unroll
        for (int j = 0; j < 4; j++)
#pragma unroll
            for (int q = 0; q < 4; q++) acc[i][j][q] = 0.f;

    const uint4* Bh4 = (const uint4*)Bh_g;
    const uint4* Bl4 = (const uint4*)Bl_g;
    float4 aR[4];
    uint4 bhR[2], blR[2];

    auto ldA = [&](int kc) {
        int k0a = kc * 64;
#pragma unroll
        for (int i = 0; i < 4; i++) {
            int u = i * 512 + tid;
            int row = u >> 4, f4 = u & 15;
            int t = t0 + row;
            float4 x = *(const float4*)(emb + (size_t)t * CD + k0a + f4 * 4);
            float4 p4 = *(const float4*)(pt + (size_t)(spos[row] + shift) * CD + k0a + f4 * 4);
            x.x += p4.x; x.y += p4.y; x.z += p4.z; x.w += p4.w;
            if (saveq) {
                size_t gi = (size_t)t * CD + k0a + f4 * 4;
                *(float4*)(g_qc + gi) = x;
                uint32_t h01, l01, h23, l23;
                split_pack(x.x, x.y, h01, l01);
                split_pack(x.z, x.w, h23, l23);
                *(uint32_t*)&g_qch[gi] = h01; *(uint32_t*)&g_qch[gi + 2] = h23;
                *(uint32_t*)&g_qcl[gi] = l01; *(uint32_t*)&g_qcl[gi + 2] = l23;
            }
            aR[i] = x;
        }
    };
    auto ldB = [&](int kc) {
#pragma unroll
        for (int i = 0; i < 2; i++) {
            int u = i * 512 + tid;
            int n = u >> 3, kb16 = u & 7;
            size_t gi = (((size_t)(n0 + n) * 256 + kc * 64) >> 3) + kb16;
            bhR[i] = Bh4[gi];
            blR[i] = Bl4[gi];
        }
    };
    auto sts = [&](int s) {
        char* sb = smc + s * STG;
#pragma unroll
        for (int i = 0; i < 4; i++) {
            int u = i * 512 + tid;
            int row = u >> 4, f4 = u & 15;
            float4 x = aR[i];
            uint32_t h01, l01, h23, l23;
            split_pack(x.x, x.y, h01, l01);
            split_pack(x.z, x.w, h23, l23);
            uint32_t off = swz((uint32_t)(row * 128 + f4 * 8));
            *(uint2*)(sb + off) = make_uint2(h01, h23);
            *(uint2*)(sb + 16384 + off) = make_uint2(l01, l23);
        }
#pragma unroll
        for (int i = 0; i < 2; i++) {
            int u = i * 512 + tid;
            int n = u >> 3, kb16 = u & 7;
            uint32_t off = swz((uint32_t)(n * 128 + kb16 * 16));
            *(uint4*)(sb + 32768 + off) = bhR[i];
            *(uint4*)(sb + 49152 + off) = blR[i];
        }
    };

    ldA(0); ldB(0);
#pragma unroll 1
    for (int kc = 0; kc < 4; kc++) {
        int s = kc & 1;
        sts(s);
        if (kc + 1 < 4) { ldA(kc + 1); ldB(kc + 1); }
        __syncthreads();
        const uint32_t sb = su + s * STG;
        uint32_t arow = (uint32_t)((mw + (lane & 15)) * 128 + (lane >> 4) * 16);
        uint32_t bn = (uint32_t)((nw + ((lane >> 4) << 3) + (lane & 7)) * 128 +
                                 ((lane >> 3) & 1) * 16);
#pragma unroll
        for (int ks = 0; ks < 4; ks++) {
            uint32_t kb = ks * 32;
            uint32_t ah[2][4], al[2][4], bh[2][4], bl[2][4];
#pragma unroll
            for (int mt = 0; mt < 2; mt++) {
                uint32_t a = sb + swz(arow + mt * 16 * 128 + kb);
                ldsm4(ah[mt], a);
                ldsm4(al[mt], a + 16384);
            }
#pragma unroll
            for (int nc = 0; nc < 2; nc++) {
                uint32_t a = sb + 32768 + swz(bn + nc * 16 * 128 + kb);
                ldsm4(bh[nc], a);
                ldsm4(bl[nc], a + 16384);
            }
#pragma unroll
            for (int mt = 0; mt < 2; mt++)
#pragma unroll
                for (int nc = 0; nc < 2; nc++) {
                    mma_bf16(acc[mt][nc * 2 + 0], ah[mt], bh[nc][0], bh[nc][1]);
                    mma_bf16(acc[mt][nc * 2 + 1], ah[mt], bh[nc][2], bh[nc][3]);
                    mma_bf16(acc[mt][nc * 2 + 0], al[mt], bh[nc][0], bh[nc][1]);
                    mma_bf16(acc[mt][nc * 2 + 1], al[mt], bh[nc][2], bh[nc][3]);
                    mma_bf16(acc[mt][nc * 2 + 0], ah[mt], bl[nc][0], bl[nc][1]);
                    mma_bf16(acc[mt][nc * 2 + 1], ah[mt], bl[nc][2], bl[nc][3]);
                }
        }
    }

    // epilogue: bf16 outputs
#pragma unroll
    for (int mt = 0; mt < 2; mt++) {
#pragma unroll
        for (int nt = 0; nt < 4; nt++) {
            int row = t0 + mw + mt * 16 + (lane >> 2);
            int col = n0 + nw + nt * 8 + (lane & 3) * 2;
            float2 b2 = *(const float2*)(bias + col);
            float2 d0 = make_float2(acc[mt][nt][0] + b2.x, acc[mt][nt][1] + b2.y);
            float2 d1 = make_float2(acc[mt][nt][2] + b2.x, acc[mt][nt][3] + b2.y);
            size_t i0 = (size_t)row * CD + col, i1 = (size_t)(row + 8) * CD + col;
            if (z == 0) {
                uint32_t h, l;
                split_pack(d0.x * 0.125f, d0.y * 0.125f, h, l);
                *(uint32_t*)&g_Qh[i0] = h; *(uint32_t*)&g_Ql[i0] = l;
                split_pack(d1.x * 0.125f, d1.y * 0.125f, h, l);
                *(uint32_t*)&g_Qh[i1] = h; *(uint32_t*)&g_Ql[i1] = l;
            } else if (z == 1) {
                uint32_t h, l;
                split_pack(d0.x, d0.y, h, l);
                *(uint32_t*)&g_Kh[i0] = h; *(uint32_t*)&g_Kl[i0] = l;
                split_pack(d1.x, d1.y, h, l);
                *(uint32_t*)&g_Kh[i1] = h; *(uint32_t*)&g_Kl[i1] = l;
            } else {
                __nv_bfloat162 v0 = __float22bfloat162_rn(d0);
                __nv_bfloat162 v1 = __float22bfloat162_rn(d1);
                *(uint32_t*)&g_Vb[i0] = *(uint32_t*)&v0;
                *(uint32_t*)&g_Vb[i1] = *(uint32_t*)&v1;
            }
        }
    }
}

// ---------------------------------------------------------------------------
// Pure-bf16 cp.async 3-stage GEMM. MODE 1: ctx@Wo -> g_tmp (raw fp32).
// MODE 2: [h|qcat]@Wm + bm -> gelu -> out.
// ---------------------------------------------------------------------------
template <int MODE>
__global__ __launch_bounds__(512, 1) void k_gemm2(
    const float* __restrict__ bias, float* __restrict__ outp) {
    extern __shared__ char smc[];
    const uint32_t su = smem_u32(smc);
    constexpr int KW = (MODE == 2) ? 512 : 256;
    constexpr int NCH = KW / 64;
    const int t0 = blockIdx.x * TM, n0 = blockIdx.y * 128;
    const int tid = threadIdx.x, w = tid >> 5, lane = tid & 31;
    const int mw = (w & 3) * 32, nw = (w >> 2) * 32;

    auto issue = [&](int kc) {
        uint32_t sb = su + (kc % 3) * STG;
        const __nv_bfloat16 *Ah_g, *Al_g;
        int k0a;
        if (MODE == 2) {
            Ah_g = (kc < 4) ? g_hh : g_qch;
            Al_g = (kc < 4) ? g_hl : g_qcl;
            k0a = (kc & 3) * 64;
        } else { Ah_g = g_ch; Al_g = g_cl; k0a = kc * 64; }
#pragma unroll
        for (int i = 0; i < 2; i++) {
            int u = i * 512 + tid;
            int row = u >> 3, g8 = u & 7;
            size_t so = (size_t)(t0 + row) * CD + k0a + g8 * 8;
            uint32_t off = swz((uint32_t)(row * 128 + g8 * 16));
            cp16(sb + off, Ah_g + so);
            cp16(sb + 16384 + off, Al_g + so);
        }
        const __nv_bfloat16* Bh_g = (MODE == 2) ? g_wtm_h : g_wto_h;
        const __nv_bfloat16* Bl_g = (MODE == 2) ? g_wtm_l : g_wto_l;
#pragma unroll
        for (int i = 0; i < 2; i++) {
            int u = i * 512 + tid;
            int n = u >> 3, g8 = u & 7;
            size_t so = (size_t)(n0 + n) * KW + kc * 64 + g8 * 8;
            uint32_t off = swz((uint32_t)(n * 128 + g8 * 16));
            cp16(sb + 32768 + off, Bh_g + so);
            cp16(sb + 49152 + off, Bl_g + so);
        }
    };

    float acc[2][4][4];
#pragma unroll
    for (int i = 0; i < 2; i++)
#pragma unroll
        for (int j = 0; j < 4; j++)
#pragma unroll
            for (int q = 0; q < 4; q++) acc[i][j][q] = 0.f;

    issue(0); CP_COMMIT();
    issue(1); CP_COMMIT();
#pragma unroll 1
    for (int kc = 0; kc < NCH; kc++) {
        CP_WAIT1();
        __syncthreads();
        if (kc + 2 < NCH) issue(kc + 2);
        CP_COMMIT();
        const uint32_t sb = su + (kc % 3) * STG;
        uint32_t arow = (uint32_t)((mw + (lane & 15)) * 128 + (lane >> 4) * 16);
        uint32_t bn = (uint32_t)((nw + ((lane >> 4) << 3) + (lane & 7)) * 128 +
                                 ((lane >> 3) & 1) * 16);
#pragma unroll
        for (int ks = 0; ks < 4; ks++) {
            uint32_t kb = ks * 32;
            uint32_t ah[2][4], al[2][4], bh[2][4], bl[2][4];
#pragma unroll
            for (int mt = 0; mt < 2; mt++) {
                uint32_t a = sb + swz(arow + mt * 16 * 128 + kb);
                ldsm4(ah[mt], a);
                ldsm4(al[mt], a + 16384);
            }
#pragma unroll
            for (int nc = 0; nc < 2; nc++) {
                uint32_t a = sb + 32768 + swz(bn + nc * 16 * 128 + kb);
                ldsm4(bh[nc], a);
                ldsm4(bl[nc], a + 16384);
            }
#pragma unroll
            for (int mt = 0; mt < 2; mt++)
#pragma unroll
                for (int nc = 0; nc < 2; nc++) {
                    mma_bf16(acc[mt][nc * 2 + 0], ah[mt], bh[nc][0], bh[nc][1]);
                    mma_bf16(acc[mt][nc * 2 + 1], ah[mt], bh[nc][2], bh[nc][3]);
                    mma_bf16(acc[mt][nc * 2 + 0], al[mt], bh[nc][0], bh[nc][1]);
                    mma_bf16(acc[mt][nc * 2 + 1], al[mt], bh[nc][2], bh[nc][3]);
                    mma_bf16(acc[mt][nc * 2 + 0], ah[mt], bl[nc][0], bl[nc][1]);
                    mma_bf16(acc[mt][nc * 2 + 1], ah[mt], bl[nc][2], bl[nc][3]);
                }
        }
    }

    float* op = (MODE == 1) ? g_tmp : outp;
    const float r2 = 0.70710678118654752440f;
#pragma unroll
    for (int mt = 0; mt < 2; mt++) {
#pragma unroll
        for (int nt = 0; nt < 4; nt++) {
            int row = t0 + mw + mt * 16 + (lane >> 2);
            int col = n0 + nw + nt * 8 + (lane & 3) * 2;
            float2 d0 = make_float2(acc[mt][nt][0], acc[mt][nt][1]);
            float2 d1 = make_float2(acc[mt][nt][2], acc[mt][nt][3]);
            if (MODE == 2) {
                float2 b2 = *(const float2*)(bias + col);
                d0.x += b2.x; d0.y += b2.y;
                d1.x += b2.x; d1.y += b2.y;
                d0.x = 0.5f * d0.x * (1.f + erff(d0.x * r2));
                d0.y = 0.5f * d0.y * (1.f + erff(d0.y * r2));
                d1.x = 0.5f * d1.x * (1.f + erff(d1.x * r2));
                d1.y = 0.5f * d1.y * (1.f + erff(d1.y * r2));
            }
            *(float2*)(op + (size_t)row * CD + col) = d0;
            *(float2*)(op + (size_t)(row + 8) * CD + col) = d1;
        }
    }
}

// ---------------------------------------------------------------------------
// LN: g_hh/g_hl = split(LayerNorm(g_tmp + bo + g_qc))
// ---------------------------------------------------------------------------
__global__ __launch_bounds__(256) void k_ln(
    const float* __restrict__ bo, const float* __restrict__ lng,
    const float* __restrict__ lnb) {
    int w = threadIdx.x >> 5, lane = threadIdx.x & 31;
    int r = blockIdx.x * 8 + w;
    int c0 = lane * 8;
    float4 t0 = *(const float4*)(g_tmp + (size_t)r * CD + c0);
    float4 t1 = *(const float4*)(g_tmp + (size_t)r * CD + c0 + 4);
    float4 q0 = *(const float4*)(g_qc + (size_t)r * CD + c0);
    float4 q1 = *(const float4*)(g_qc + (size_t)r * CD + c0 + 4);
    float4 b0 = *(const float4*)(bo + c0);
    float4 b1 = *(const float4*)(bo + c0 + 4);
    float v[8];
    v[0] = t0.x + q0.x + b0.x; v[1] = t0.y + q0.y + b0.y;
    v[2] = t0.z + q0.z + b0.z; v[3] = t0.w + q0.w + b0.w;
    v[4] = t1.x + q1.x + b1.x; v[5] = t1.y + q1.y + b1.y;
    v[6] = t1.z + q1.z + b1.z; v[7] = t1.w + q1.w + b1.w;
    float s1 = 0.f, s2 = 0.f;
#pragma unroll
    for (int i = 0; i < 8; i++) { s1 += v[i]; s2 += v[i] * v[i]; }
#pragma unroll
    for (int o = 16; o; o >>= 1) {
        s1 += __shfl_xor_sync(0xffffffffu, s1, o);
        s2 += __shfl_xor_sync(0xffffffffu, s2, o);
    }
    float mu = s1 * (1.f / CD);
    float rs = rsqrtf(s2 * (1.f / CD) - mu * mu + 1e-12f);
    float4 g0 = *(const float4*)(lng + c0);
    float4 g1 = *(const float4*)(lng + c0 + 4);
    float4 bb0 = *(const float4*)(lnb + c0);
    float4 bb1 = *(const float4*)(lnb + c0 + 4);
    float o8[8];
    o8[0] = (v[0] - mu) * rs * g0.x + bb0.x; o8[1] = (v[1] - mu) * rs * g0.y + bb0.y;
    o8[2] = (v[2] - mu) * rs * g0.z + bb0.z; o8[3] = (v[3] - mu) * rs * g0.w + bb0.w;
    o8[4] = (v[4] - mu) * rs * g1.x + bb1.x; o8[5] = (v[5] - mu) * rs * g1.y + bb1.y;
    o8[6] = (v[6] - mu) * rs * g1.z + bb1.z; o8[7] = (v[7] - mu) * rs * g1.w + bb1.w;
    size_t base = (size_t)r * CD + c0;
#pragma unroll
    for (int i = 0; i < 4; i++) {
        uint32_t h, l;
        split_pack(o8[2 * i], o8[2 * i + 1], h, l);
        *(uint32_t*)&g_hh[base + 2 * i] = h;
        *(uint32_t*)&g_hl[base + 2 * i] = l;
    }
}

// ---------------------------------------------------------------------------
// Flash attention: inputs pre-split bf16; cp.async staging; ctx out split bf16.
// ---------------------------------------------------------------------------
#define QH_OFF 0
#define QL_OFF 32768
#define KH_OFF 65536
#define KL_OFF 98304
#define VT_OFF 131072
#define ATT_SMEM 163840

__global__ __launch_bounds__(256, 1) void k_attn(const int* __restrict__ sl) {
    extern __shared__ char smc[];
    const uint32_t su = smem_u32(smc);
    int b = g_order[blockIdx.x], h = blockIdx.y;
    int L = sl[b], start = g_starts[b], hoff = h * CHD;
    int tid = threadIdx.x;
    int nch = (L + 63) >> 6, RR = nch * 64;

    // Q/K hi/lo: pure cp.async copy (zero-fill beyond L)
    {
        const __nv_bfloat16* sp[4] = {g_Qh, g_Ql, g_Kh, g_Kl};
        const uint32_t dst[4] = {QH_OFF, QL_OFF, KH_OFF, KL_OFF};
#pragma unroll
        for (int arr = 0; arr < 4; arr++) {
#pragma unroll 1
            for (int u = tid; u < RR * 8; u += 256) {
                int row = u >> 3, g8 = u & 7;
                int rsrc = min(row, L - 1);
                const void* src = sp[arr] + (size_t)(start + rsrc) * CD + hoff + g8 * 8;
                cp16z(su + dst[arr] + swz((uint32_t)(row * 128 + g8 * 16)), src, row < L);
            }
        }
        CP_COMMIT();
    }
    // V transpose staging from bf16
#pragma unroll 1
    for (int u = tid; u < RR * 8; u += 256) {
        int row = u >> 3, g8 = u & 7;
        int d0 = g8 * 8;
        uint4 x = make_uint4(0, 0, 0, 0);
        if (row < L)
            x = *(const uint4*)(g_Vb + (size_t)(start + row) * CD + hoff + d0);
        const __nv_bfloat16* pv = (const __nv_bfloat16*)&x;
        uint32_t cb = VT_OFF + (row >> 6) * 8192;
        int kin2 = (row & 63) * 2;
#pragma unroll
        for (int i = 0; i < 8; i++)
            *(__nv_bfloat16*)(smc + cb + swz((uint32_t)((d0 + i) * 128 + kin2))) = pv[i];
    }
    CP_WAIT0();
    __syncthreads();

    int w = tid >> 5, lane = tid & 31;
    int q0w = w * 32;
    if (q0w >= L) return;

    float O[2][8][4];
#pragma unroll
    for (int mt = 0; mt < 2; mt++)
#pragma unroll
        for (int nt = 0; nt < 8; nt++)
#pragma unroll
            for (int e = 0; e < 4; e++) O[mt][nt][e] = 0.f;
    float m_run[2][2] = {{0.f, 0.f}, {0.f, 0.f}};
    float l_run[2][2] = {{1.f, 1.f}, {1.f, 1.f}};

#pragma unroll 1
    for (int c = 0; c < nch; c++) {
        int j0 = c * 64;
        float S[2][8][4];
#pragma unroll
        for (int mt = 0; mt < 2; mt++)
#pragma unroll
            for (int nt = 0; nt < 8; nt++)
#pragma unroll
                for (int e = 0; e < 4; e++) S[mt][nt][e] = 0.f;

#pragma unroll
        for (int ks = 0; ks < 4; ks++) {
            uint32_t aH[2][4], aL[2][4];
#pragma unroll
            for (int mt = 0; mt < 2; mt++) {
                uint32_t ao = swz((uint32_t)((q0w + mt * 16 + (lane & 15)) * 128 +
                                             (lane >> 4) * 16 + ks * 32));
                ldsm4(aH[mt], su + QH_OFF + ao);
                ldsm4(aL[mt], su + QL_OFF + ao);
            }
#pragma unroll
            for (int p = 0; p < 4; p++) {
                uint32_t bo_ = swz((uint32_t)((j0 + p * 16 + ((lane >> 4) << 3) + (lane & 7)) * 128 +
                                              ((lane >> 3) & 1) * 16 + ks * 32));
                uint32_t bh[4], bl[4];
                ldsm4(bh, su + KH_OFF + bo_);
                ldsm4(bl, su + KL_OFF + bo_);
#pragma unroll
                for (int mt = 0; mt < 2; mt++) {
                    mma_bf16(S[mt][2 * p], aH[mt], bh[0], bh[1]);
                    mma_bf16(S[mt][2 * p + 1], aH[mt], bh[2], bh[3]);
                    mma_bf16(S[mt][2 * p], aL[mt], bh[0], bh[1]);
                    mma_bf16(S[mt][2 * p + 1], aL[mt], bh[2], bh[3]);
                    mma_bf16(S[mt][2 * p], aH[mt], bl[0], bl[1]);
                    mma_bf16(S[mt][2 * p + 1], aH[mt], bl[2], bl[3]);
                }
            }
        }

        int col01 = j0 + (lane & 3) * 2;
#pragma unroll
        for (int mt = 0; mt < 2; mt++) {
#pragma unroll
            for (int nt = 0; nt < 8; nt++) {
                int base = col01 + nt * 8;
                if (base >= L)     { S[mt][nt][0] = -1e30f; S[mt][nt][2] = -1e30f; }
                if (base + 1 >= L) { S[mt][nt][1] = -1e30f; S[mt][nt][3] = -1e30f; }
            }
            float rmA = -1e30f, rmB = -1e30f;
#pragma unroll
            for (int nt = 0; nt < 8; nt++) {
                rmA = fmaxf(rmA, fmaxf(S[mt][nt][0], S[mt][nt][1]));
                rmB = fmaxf(rmB, fmaxf(S[mt][nt][2], S[mt][nt][3]));
            }
            rmA = q2max(rmA); rmB = q2max(rmB);
            float mA = fmaxf(m_run[mt][0], rmA), mB = fmaxf(m_run[mt][1], rmB);
            float aA = __expf(m_run[mt][0] - mA), aB = __expf(m_run[mt][1] - mB);
            m_run[mt][0] = mA; m_run[mt][1] = mB;
            float sA = 0.f, sB = 0.f;
#pragma unroll
            for (int nt = 0; nt < 8; nt++) {
                S[mt][nt][0] = __expf(S[mt][nt][0] - mA);
                S[mt][nt][1] = __expf(S[mt][nt][1] - mA);
                S[mt][nt][2] = __expf(S[mt][nt][2] - mB);
                S[mt][nt][3] = __expf(S[mt][nt][3] - mB);
                sA += S[mt][nt][0] + S[mt][nt][1];
                sB += S[mt][nt][2] + S[mt][nt][3];
            }
            sA = q2sum(sA); sB = q2sum(sB);
            l_run[mt][0] = l_run[mt][0] * aA + sA;
            l_run[mt][1] = l_run[mt][1] * aB + sB;
#pragma unroll
            for (int nt = 0; nt < 8; nt++) {
                O[mt][nt][0] *= aA; O[mt][nt][1] *= aA;
                O[mt][nt][2] *= aB; O[mt][nt][3] *= aB;
            }
        }

#pragma unroll
        for (int pt = 0; pt < 4; pt++) {
            uint32_t vb[4][4];
#pragma unroll
            for (int np = 0; np < 4; np++) {
                uint32_t vo = swz((uint32_t)((np * 16 + ((lane >> 4) << 3) + (lane & 7)) * 128 +
                                             ((lane >> 3) & 1) * 16 + pt * 32));
                ldsm4(vb[np], su + VT_OFF + c * 8192 + vo);
            }
#pragma unroll
            for (int mt = 0; mt < 2; mt++) {
                uint32_t pa[4], pl[4];
                split_pack(S[mt][2 * pt][0], S[mt][2 * pt][1], pa[0], pl[0]);
                split_pack(S[mt][2 * pt][2], S[mt][2 * pt][3], pa[1], pl[1]);
                split_pack(S[mt][2 * pt + 1][0], S[mt][2 * pt + 1][1], pa[2], pl[2]);
                split_pack(S[mt][2 * pt + 1][2], S[mt][2 * pt + 1][3], pa[3], pl[3]);
#pragma unroll
                for (int np = 0; np < 4; np++) {
                    mma_bf16(O[mt][2 * np], pa, vb[np][0], vb[np][1]);
                    mma_bf16(O[mt][2 * np + 1], pa, vb[np][2], vb[np][3]);
                    mma_bf16(O[mt][2 * np], pl, vb[np][0], vb[np][1]);
                    mma_bf16(O[mt][2 * np + 1], pl, vb[np][2], vb[np][3]);
                }
            }
        }
    }

    // store ctx split bf16
#pragma unroll
    for (int mt = 0; mt < 2; mt++) {
        float iA = 1.f / l_run[mt][0], iB = 1.f / l_run[mt][1];
        int rA = q0w + mt * 16 + (lane >> 2);
        int rB = rA + 8;
#pragma unroll
        for (int nt = 0; nt < 8; nt++) {
            int col = hoff + nt * 8 + (lane & 3) * 2;
            if (rA < L) {
                uint32_t hh, ll;
                split_pack(O[mt][nt][0] * iA, O[mt][nt][1] * iA, hh, ll);
                size_t i0 = (size_t)(start + rA) * CD + col;
                *(uint32_t*)&g_ch[i0] = hh;
                *(uint32_t*)&g_cl[i0] = ll;
            }
            if (rB < L) {
                uint32_t hh, ll;
                split_pack(O[mt][nt][2] * iB, O[mt][nt][3] * iB, hh, ll);
                size_t i1 = (size_t)(start + rB) * CD + col;
                *(uint32_t*)&g_ch[i1] = hh;
                *(uint32_t*)&g_cl[i1] = ll;
            }
        }
    }
}

// ---------------------------------------------------------------------------
extern "C" void kernel_launch(void* const* d_in, const int* in_sizes, int n_in,
                              void* d_out, int out_size) {
    const float* qe  = (const float*)d_in[0];
    const float* ke  = (const float*)d_in[1];
    const float* ve  = (const float*)d_in[2];
    const float* pt  = (const float*)d_in[3];
    const float* wq  = (const float*)d_in[4];
    const float* bq  = (const float*)d_in[5];
    const float* wk  = (const float*)d_in[6];
    const float* bk  = (const float*)d_in[7];
    const float* wv  = (const float*)d_in[8];
    const float* bv  = (const float*)d_in[9];
    const float* wo  = (const float*)d_in[10];
    const float* bo  = (const float*)d_in[11];
    const float* lng = (const float*)d_in[12];
    const float* lnb = (const float*)d_in[13];
    const float* wm  = (const float*)d_in[14];
    const float* bm  = (const float*)d_in[15];
    const int*   sl  = (const int*)d_in[16];
    float* out = (float*)d_out;

    cudaFuncSetAttribute(k_proj, cudaFuncAttributeMaxDynamicSharedMemorySize, SMEM_P);
    cudaFuncSetAttribute(k_gemm2<1>, cudaFuncAttributeMaxDynamicSharedMemorySize, SMEM_G3);
    cudaFuncSetAttribute(k_gemm2<2>, cudaFuncAttributeMaxDynamicSharedMemorySize, SMEM_G3);
    cudaFuncSetAttribute(k_attn, cudaFuncAttributeMaxDynamicSharedMemorySize, ATT_SMEM);

    k_index<<<1, CB>>>(sl);
    k_wt<<<dim3(16, 8, 5), dim3(32, 8)>>>(wq, wk, wv, wo, wm);

    k_proj<<<dim3(GBX, 2, 3), 512, SMEM_P>>>(qe, ke, ve, pt, bq, bk, bv);
    k_attn<<<dim3(CB, CH), 256, ATT_SMEM>>>(sl);
    k_gemm2<1><<<dim3(GBX, 2), 512, SMEM_G3>>>(nullptr, nullptr);
    k_ln<<<CL1 / 8, 256>>>(bo, lng, lnb);
    k_gemm2<2><<<dim3(GBX, 2), 512, SMEM_G3>>>(bm, out);
}

// round 8
// speedup vs baseline: 2.5489x; 1.0222x over previous
#include <cuda_runtime.h>
#include <cuda_bf16.h>
#include <math.h>
#include <stdint.h>

#define CL1 32896
#define CB  256
#define CD  256
#define CH  4
#define CHD 64
#define TM  128
#define GBX 257

__device__ int   g_starts[CB];
__device__ int   g_pos[CL1];
__device__ int   g_order[CB];
__device__ float g_qc[CL1 * CD];
__device__ float g_tmp[CL1 * CD];
__device__ __nv_bfloat16 g_Qh[CL1 * CD], g_Ql[CL1 * CD];
__device__ __nv_bfloat16 g_Kh[CL1 * CD], g_Kl[CL1 * CD];
__device__ __nv_bfloat16 g_Vb[CL1 * CD];
__device__ __nv_bfloat16 g_qch[CL1 * CD], g_qcl[CL1 * CD];
__device__ __nv_bfloat16 g_ch[CL1 * CD], g_cl[CL1 * CD];
__device__ __nv_bfloat16 g_hh[CL1 * CD], g_hl[CL1 * CD];
__device__ __nv_bfloat16 g_wtq_h[CD * CD], g_wtq_l[CD * CD];
__device__ __nv_bfloat16 g_wtk_h[CD * CD], g_wtk_l[CD * CD];
__device__ __nv_bfloat16 g_wtv_h[CD * CD], g_wtv_l[CD * CD];
__device__ __nv_bfloat16 g_wto_h[CD * CD], g_wto_l[CD * CD];
__device__ __nv_bfloat16 g_wtm_h[2 * CD * CD], g_wtm_l[2 * CD * CD];

__device__ __forceinline__ uint32_t smem_u32(const void* p) {
    return (uint32_t)__cvta_generic_to_shared(p);
}
__device__ __forceinline__ uint32_t swz(uint32_t off) {
    return off ^ ((off >> 3) & 0x70);
}
__device__ __forceinline__ void ldsm4(uint32_t r[4], uint32_t addr) {
    asm volatile("ldmatrix.sync.aligned.m8n8.x4.shared.b16 {%0,%1,%2,%3}, [%4];"
                 : "=r"(r[0]), "=r"(r[1]), "=r"(r[2]), "=r"(r[3]) : "r"(addr));
}
__device__ __forceinline__ void mma_bf16(float d[4], const uint32_t a[4],
                                         uint32_t b0, uint32_t b1) {
    asm volatile("mma.sync.aligned.m16n8k16.row.col.f32.bf16.bf16.f32 "
                 "{%0,%1,%2,%3}, {%4,%5,%6,%7}, {%8,%9}, {%0,%1,%2,%3};"
                 : "+f"(d[0]), "+f"(d[1]), "+f"(d[2]), "+f"(d[3])
                 : "r"(a[0]), "r"(a[1]), "r"(a[2]), "r"(a[3]), "r"(b0), "r"(b1));
}
__device__ __forceinline__ void split_pack(float a, float b, uint32_t& h, uint32_t& l) {
    __nv_bfloat16 ha = __float2bfloat16_rn(a), hb = __float2bfloat16_rn(b);
    __nv_bfloat162 H = __halves2bfloat162(ha, hb);
    h = *(uint32_t*)&H;
    __nv_bfloat162 Lo = __float22bfloat162_rn(
        make_float2(a - __bfloat162float(ha), b - __bfloat162float(hb)));
    l = *(uint32_t*)&Lo;
}
__device__ __forceinline__ float q2max(float v) {
    v = fmaxf(v, __shfl_xor_sync(0xffffffffu, v, 1));
    return fmaxf(v, __shfl_xor_sync(0xffffffffu, v, 2));
}
__device__ __forceinline__ float q2sum(float v) {
    v += __shfl_xor_sync(0xffffffffu, v, 1);
    return v + __shfl_xor_sync(0xffffffffu, v, 2);
}
__device__ __forceinline__ void cp16(uint32_t dst, const void* src) {
    asm volatile("cp.async.cg.shared.global [%0], [%1], 16;" :: "r"(dst), "l"(src));
}
__device__ __forceinline__ void cp16z(uint32_t dst, const void* src, int do_copy) {
    asm volatile("cp.async.cg.shared.global [%0], [%1], 16, %2;"
                 :: "r"(dst), "l"(src), "r"(do_copy ? 16 : 0));
}
#define CP_COMMIT() asm volatile("cp.async.commit_group;" ::: "memory")
#define CP_WAIT1()  asm volatile("cp.async.wait_group 1;" ::: "memory")
#define CP_WAIT0()  asm volatile("cp.async.wait_group 0;" ::: "memory")

// ---------------------------------------------------------------------------
__global__ void k_index(const int* __restrict__ sl) {
    __shared__ int st[CB];
    int tid = threadIdx.x;
    if (tid == 0) {
        int a = 0;
        for (int b = 0; b < CB; b++) { st[b] = a; a += sl[b]; }
    }
    __syncthreads();
    int s = st[tid], len = sl[tid];
    g_starts[tid] = s;
    g_order[CB - len] = tid;
    for (int i = 0; i < len; i++) g_pos[s + i] = i;
}

__global__ void k_wt(const float* __restrict__ wq, const float* __restrict__ wk,
                     const float* __restrict__ wv, const float* __restrict__ wo,
                     const float* __restrict__ wm) {
    __shared__ float t[32][33];
    int z = blockIdx.z;
    const float* W; __nv_bfloat16* oh; __nv_bfloat16* ol; int K;
    switch (z) {
        case 0: W = wq; oh = g_wtq_h; ol = g_wtq_l; K = 256; break;
        case 1: W = wk; oh = g_wtk_h; ol = g_wtk_l; K = 256; break;
        case 2: W = wv; oh = g_wtv_h; ol = g_wtv_l; K = 256; break;
        case 3: W = wo; oh = g_wto_h; ol = g_wto_l; K = 256; break;
        default: W = wm; oh = g_wtm_h; ol = g_wtm_l; K = 512; break;
    }
    int k0 = blockIdx.x * 32, n0 = blockIdx.y * 32;
    if (k0 >= K) return;
    int tx = threadIdx.x, ty = threadIdx.y;
#pragma unroll
    for (int i = 0; i < 4; i++)
        t[ty + 8 * i][tx] = W[(size_t)(k0 + ty + 8 * i) * CD + n0 + tx];
    __syncthreads();
#pragma unroll
    for (int i = 0; i < 4; i++) {
        int rr = ty + 8 * i;
        float v = t[tx][rr];
        __nv_bfloat16 h = __float2bfloat16_rn(v);
        oh[(size_t)(n0 + rr) * K + k0 + tx] = h;
        ol[(size_t)(n0 + rr) * K + k0 + tx] = __float2bfloat16_rn(v - __bfloat162float(h));
    }
}

// ---------------------------------------------------------------------------
#define STG 65536
#define SMEM_P (2 * STG)
#define SMEM_G3 (3 * STG)

// Projections: z = 0(Q) 1(K) 2(V)
__global__ __launch_bounds__(512, 1) void k_proj(
    const float* __restrict__ qe, const float* __restrict__ ke,
    const float* __restrict__ ve, const float* __restrict__ pt,
    const float* __restrict__ bq, const float* __restrict__ bk,
    const float* __restrict__ bv) {
    extern __shared__ char smc[];
    const uint32_t su = smem_u32(smc);
    const int z = blockIdx.z;
    const float* emb = z == 0 ? qe : (z == 1 ? ke : ve);
    const __nv_bfloat16* Bh_g = z == 0 ? g_wtq_h : (z == 1 ? g_wtk_h : g_wtv_h);
    const __nv_bfloat16* Bl_g = z == 0 ? g_wtq_l : (z == 1 ? g_wtk_l : g_wtv_l);
    const float* bias = z == 0 ? bq : (z == 1 ? bk : bv);
    const int shift = (z == 0) ? 1 : 0;
    const bool saveq = (z == 0);
    const int t0 = blockIdx.x * TM, n0 = blockIdx.y * 128;
    const int tid = threadIdx.x, w = tid >> 5, lane = tid & 31;
    const int mw = (w & 3) * 32, nw = (w >> 2) * 32;

    __shared__ int spos[TM];
    if (tid < TM) spos[tid] = g_pos[t0 + tid];
    __syncthreads();

    float acc[2][4][4];
#pragma unroll
    for (int i = 0; i < 2; i++)
#pragma unroll
        for (int j = 0; j < 4; j++)
#pragma unroll
            for (int q = 0; q < 4; q++) acc[i][j][q] = 0.f;

    const uint4* Bh4 = (const uint4*)Bh_g;
    const uint4* Bl4 = (const uint4*)Bl_g;
    float4 aR[4];
    uint4 bhR[2], blR[2];

    auto ldA = [&](int kc) {
        int k0a = kc * 64;
#pragma unroll
        for (int i = 0; i < 4; i++) {
            int u = i * 512 + tid;
            int row = u >> 4, f4 = u & 15;
            int t = t0 + row;
            float4 x = *(const float4*)(emb + (size_t)t * CD + k0a + f4 * 4);
            float4 p4 = *(const float4*)(pt + (size_t)(spos[row] + shift) * CD + k0a + f4 * 4);
            x.x += p4.x; x.y += p4.y; x.z += p4.z; x.w += p4.w;
            if (saveq) {
                size_t gi = (size_t)t * CD + k0a + f4 * 4;
                *(float4*)(g_qc + gi) = x;
                uint32_t h01, l01, h23, l23;
                split_pack(x.x, x.y, h01, l01);
                split_pack(x.z, x.w, h23, l23);
                *(uint32_t*)&g_qch[gi] = h01; *(uint32_t*)&g_qch[gi + 2] = h23;
                *(uint32_t*)&g_qcl[gi] = l01; *(uint32_t*)&g_qcl[gi + 2] = l23;
            }
            aR[i] = x;
        }
    };
    auto ldB = [&](int kc) {
#pragma unroll
        for (int i = 0; i < 2; i++) {
            int u = i * 512 + tid;
            int n = u >> 3, kb16 = u & 7;
            size_t gi = (((size_t)(n0 + n) * 256 + kc * 64) >> 3) + kb16;
            bhR[i] = Bh4[gi];
            blR[i] = Bl4[gi];
        }
    };
    auto sts = [&](int s) {
        char* sb = smc + s * STG;
#pragma unroll
        for (int i = 0; i < 4; i++) {
            int u = i * 512 + tid;
            int row = u >> 4, f4 = u & 15;
            float4 x = aR[i];
            uint32_t h01, l01, h23, l23;
            split_pack(x.x, x.y, h01, l01);
            split_pack(x.z, x.w, h23, l23);
            uint32_t off = swz((uint32_t)(row * 128 + f4 * 8));
            *(uint2*)(sb + off) = make_uint2(h01, h23);
            *(uint2*)(sb + 16384 + off) = make_uint2(l01, l23);
        }
#pragma unroll
        for (int i = 0; i < 2; i++) {
            int u = i * 512 + tid;
            int n = u >> 3, kb16 = u & 7;
            uint32_t off = swz((uint32_t)(n * 128 + kb16 * 16));
            *(uint4*)(sb + 32768 + off) = bhR[i];
            *(uint4*)(sb + 49152 + off) = blR[i];
        }
    };

    ldA(0); ldB(0);
#pragma unroll 1
    for (int kc = 0; kc < 4; kc++) {
        int s = kc & 1;
        sts(s);
        if (kc + 1 < 4) { ldA(kc + 1); ldB(kc + 1); }
        __syncthreads();
        const uint32_t sb = su + s * STG;
        uint32_t arow = (uint32_t)((mw + (lane & 15)) * 128 + (lane >> 4) * 16);
        uint32_t bn = (uint32_t)((nw + ((lane >> 4) << 3) + (lane & 7)) * 128 +
                                 ((lane >> 3) & 1) * 16);
#pragma unroll
        for (int ks = 0; ks < 4; ks++) {
            uint32_t kb = ks * 32;
            uint32_t ah[2][4], al[2][4], bh[2][4], bl[2][4];
#pragma unroll
            for (int mt = 0; mt < 2; mt++) {
                uint32_t a = sb + swz(arow + mt * 16 * 128 + kb);
                ldsm4(ah[mt], a);
                ldsm4(al[mt], a + 16384);
            }
#pragma unroll
            for (int nc = 0; nc < 2; nc++) {
                uint32_t a = sb + 32768 + swz(bn + nc * 16 * 128 + kb);
                ldsm4(bh[nc], a);
                ldsm4(bl[nc], a + 16384);
            }
#pragma unroll
            for (int mt = 0; mt < 2; mt++)
#pragma unroll
                for (int nc = 0; nc < 2; nc++) {
                    mma_bf16(acc[mt][nc * 2 + 0], ah[mt], bh[nc][0], bh[nc][1]);
                    mma_bf16(acc[mt][nc * 2 + 1], ah[mt], bh[nc][2], bh[nc][3]);
                    mma_bf16(acc[mt][nc * 2 + 0], al[mt], bh[nc][0], bh[nc][1]);
                    mma_bf16(acc[mt][nc * 2 + 1], al[mt], bh[nc][2], bh[nc][3]);
                    mma_bf16(acc[mt][nc * 2 + 0], ah[mt], bl[nc][0], bl[nc][1]);
                    mma_bf16(acc[mt][nc * 2 + 1], ah[mt], bl[nc][2], bl[nc][3]);
                }
        }
    }

#pragma unroll
    for (int mt = 0; mt < 2; mt++) {
#pragma unroll
        for (int nt = 0; nt < 4; nt++) {
            int row = t0 + mw + mt * 16 + (lane >> 2);
            int col = n0 + nw + nt * 8 + (lane & 3) * 2;
            float2 b2 = *(const float2*)(bias + col);
            float2 d0 = make_float2(acc[mt][nt][0] + b2.x, acc[mt][nt][1] + b2.y);
            float2 d1 = make_float2(acc[mt][nt][2] + b2.x, acc[mt][nt][3] + b2.y);
            size_t i0 = (size_t)row * CD + col, i1 = (size_t)(row + 8) * CD + col;
            if (z == 0) {
                uint32_t h, l;
                split_pack(d0.x * 0.125f, d0.y * 0.125f, h, l);
                *(uint32_t*)&g_Qh[i0] = h; *(uint32_t*)&g_Ql[i0] = l;
                split_pack(d1.x * 0.125f, d1.y * 0.125f, h, l);
                *(uint32_t*)&g_Qh[i1] = h; *(uint32_t*)&g_Ql[i1] = l;
            } else if (z == 1) {
                uint32_t h, l;
                split_pack(d0.x, d0.y, h, l);
                *(uint32_t*)&g_Kh[i0] = h; *(uint32_t*)&g_Kl[i0] = l;
                split_pack(d1.x, d1.y, h, l);
                *(uint32_t*)&g_Kh[i1] = h; *(uint32_t*)&g_Kl[i1] = l;
            } else {
                __nv_bfloat162 v0 = __float22bfloat162_rn(d0);
                __nv_bfloat162 v1 = __float22bfloat162_rn(d1);
                *(uint32_t*)&g_Vb[i0] = *(uint32_t*)&v0;
                *(uint32_t*)&g_Vb[i1] = *(uint32_t*)&v1;
            }
        }
    }
}

// ---------------------------------------------------------------------------
template <int MODE>
__global__ __launch_bounds__(512, 1) void k_gemm2(
    const float* __restrict__ bias, float* __restrict__ outp) {
    extern __shared__ char smc[];
    const uint32_t su = smem_u32(smc);
    constexpr int KW = (MODE == 2) ? 512 : 256;
    constexpr int NCH = KW / 64;
    const int t0 = blockIdx.x * TM, n0 = blockIdx.y * 128;
    const int tid = threadIdx.x, w = tid >> 5, lane = tid & 31;
    const int mw = (w & 3) * 32, nw = (w >> 2) * 32;

    auto issue = [&](int kc) {
        uint32_t sb = su + (kc % 3) * STG;
        const __nv_bfloat16 *Ah_g, *Al_g;
        int k0a;
        if (MODE == 2) {
            Ah_g = (kc < 4) ? g_hh : g_qch;
            Al_g = (kc < 4) ? g_hl : g_qcl;
            k0a = (kc & 3) * 64;
        } else { Ah_g = g_ch; Al_g = g_cl; k0a = kc * 64; }
#pragma unroll
        for (int i = 0; i < 2; i++) {
            int u = i * 512 + tid;
            int row = u >> 3, g8 = u & 7;
            size_t so = (size_t)(t0 + row) * CD + k0a + g8 * 8;
            uint32_t off = swz((uint32_t)(row * 128 + g8 * 16));
            cp16(sb + off, Ah_g + so);
            cp16(sb + 16384 + off, Al_g + so);
        }
        const __nv_bfloat16* Bh_g = (MODE == 2) ? g_wtm_h : g_wto_h;
        const __nv_bfloat16* Bl_g = (MODE == 2) ? g_wtm_l : g_wto_l;
#pragma unroll
        for (int i = 0; i < 2; i++) {
            int u = i * 512 + tid;
            int n = u >> 3, g8 = u & 7;
            size_t so = (size_t)(n0 + n) * KW + kc * 64 + g8 * 8;
            uint32_t off = swz((uint32_t)(n * 128 + g8 * 16));
            cp16(sb + 32768 + off, Bh_g + so);
            cp16(sb + 49152 + off, Bl_g + so);
        }
    };

    float acc[2][4][4];
#pragma unroll
    for (int i = 0; i < 2; i++)
#pragma unroll
        for (int j = 0; j < 4; j++)
#pragma unroll
            for (int q = 0; q < 4; q++) acc[i][j][q] = 0.f;

    issue(0); CP_COMMIT();
    issue(1); CP_COMMIT();
#pragma unroll 1
    for (int kc = 0; kc < NCH; kc++) {
        CP_WAIT1();
        __syncthreads();
        if (kc + 2 < NCH) issue(kc + 2);
        CP_COMMIT();
        const uint32_t sb = su + (kc % 3) * STG;
        uint32_t arow = (uint32_t)((mw + (lane & 15)) * 128 + (lane >> 4) * 16);
        uint32_t bn = (uint32_t)((nw + ((lane >> 4) << 3) + (lane & 7)) * 128 +
                                 ((lane >> 3) & 1) * 16);
#pragma unroll
        for (int ks = 0; ks < 4; ks++) {
            uint32_t kb = ks * 32;
            uint32_t ah[2][4], al[2][4], bh[2][4], bl[2][4];
#pragma unroll
            for (int mt = 0; mt < 2; mt++) {
                uint32_t a = sb + swz(arow + mt * 16 * 128 + kb);
                ldsm4(ah[mt], a);
                ldsm4(al[mt], a + 16384);
            }
#pragma unroll
            for (int nc = 0; nc < 2; nc++) {
                uint32_t a = sb + 32768 + swz(bn + nc * 16 * 128 + kb);
                ldsm4(bh[nc], a);
                ldsm4(bl[nc], a + 16384);
            }
#pragma unroll
            for (int mt = 0; mt < 2; mt++)
#pragma unroll
                for (int nc = 0; nc < 2; nc++) {
                    mma_bf16(acc[mt][nc * 2 + 0], ah[mt], bh[nc][0], bh[nc][1]);
                    mma_bf16(acc[mt][nc * 2 + 1], ah[mt], bh[nc][2], bh[nc][3]);
                    mma_bf16(acc[mt][nc * 2 + 0], al[mt], bh[nc][0], bh[nc][1]);
                    mma_bf16(acc[mt][nc * 2 + 1], al[mt], bh[nc][2], bh[nc][3]);
                    mma_bf16(acc[mt][nc * 2 + 0], ah[mt], bl[nc][0], bl[nc][1]);
                    mma_bf16(acc[mt][nc * 2 + 1], ah[mt], bl[nc][2], bl[nc][3]);
                }
        }
    }

    float* op = (MODE == 1) ? g_tmp : outp;
    const float r2 = 0.70710678118654752440f;
#pragma unroll
    for (int mt = 0; mt < 2; mt++) {
#pragma unroll
        for (int nt = 0; nt < 4; nt++) {
            int row = t0 + mw + mt * 16 + (lane >> 2);
            int col = n0 + nw + nt * 8 + (lane & 3) * 2;
            float2 d0 = make_float2(acc[mt][nt][0], acc[mt][nt][1]);
            float2 d1 = make_float2(acc[mt][nt][2], acc[mt][nt][3]);
            if (MODE == 2) {
                float2 b2 = *(const float2*)(bias + col);
                d0.x += b2.x; d0.y += b2.y;
                d1.x += b2.x; d1.y += b2.y;
                d0.x = 0.5f * d0.x * (1.f + erff(d0.x * r2));
                d0.y = 0.5f * d0.y * (1.f + erff(d0.y * r2));
                d1.x = 0.5f * d1.x * (1.f + erff(d1.x * r2));
                d1.y = 0.5f * d1.y * (1.f + erff(d1.y * r2));
            }
            *(float2*)(op + (size_t)row * CD + col) = d0;
            *(float2*)(op + (size_t)(row + 8) * CD + col) = d1;
        }
    }
}

// ---------------------------------------------------------------------------
__global__ __launch_bounds__(256) void k_ln(
    const float* __restrict__ bo, const float* __restrict__ lng,
    const float* __restrict__ lnb) {
    int w = threadIdx.x >> 5, lane = threadIdx.x & 31;
    int r = blockIdx.x * 8 + w;
    int c0 = lane * 8;
    float4 t0 = *(const float4*)(g_tmp + (size_t)r * CD + c0);
    float4 t1 = *(const float4*)(g_tmp + (size_t)r * CD + c0 + 4);
    float4 q0 = *(const float4*)(g_qc + (size_t)r * CD + c0);
    float4 q1 = *(const float4*)(g_qc + (size_t)r * CD + c0 + 4);
    float4 b0 = *(const float4*)(bo + c0);
    float4 b1 = *(const float4*)(bo + c0 + 4);
    float v[8];
    v[0] = t0.x + q0.x + b0.x; v[1] = t0.y + q0.y + b0.y;
    v[2] = t0.z + q0.z + b0.z; v[3] = t0.w + q0.w + b0.w;
    v[4] = t1.x + q1.x + b1.x; v[5] = t1.y + q1.y + b1.y;
    v[6] = t1.z + q1.z + b1.z; v[7] = t1.w + q1.w + b1.w;
    float s1 = 0.f, s2 = 0.f;
#pragma unroll
    for (int i = 0; i < 8; i++) { s1 += v[i]; s2 += v[i] * v[i]; }
#pragma unroll
    for (int o = 16; o; o >>= 1) {
        s1 += __shfl_xor_sync(0xffffffffu, s1, o);
        s2 += __shfl_xor_sync(0xffffffffu, s2, o);
    }
    float mu = s1 * (1.f / CD);
    float rs = rsqrtf(s2 * (1.f / CD) - mu * mu + 1e-12f);
    float4 g0 = *(const float4*)(lng + c0);
    float4 g1 = *(const float4*)(lng + c0 + 4);
    float4 bb0 = *(const float4*)(lnb + c0);
    float4 bb1 = *(const float4*)(lnb + c0 + 4);
    float o8[8];
    o8[0] = (v[0] - mu) * rs * g0.x + bb0.x; o8[1] = (v[1] - mu) * rs * g0.y + bb0.y;
    o8[2] = (v[2] - mu) * rs * g0.z + bb0.z; o8[3] = (v[3] - mu) * rs * g0.w + bb0.w;
    o8[4] = (v[4] - mu) * rs * g1.x + bb1.x; o8[5] = (v[5] - mu) * rs * g1.y + bb1.y;
    o8[6] = (v[6] - mu) * rs * g1.z + bb1.z; o8[7] = (v[7] - mu) * rs * g1.w + bb1.w;
    size_t base = (size_t)r * CD + c0;
#pragma unroll
    for (int i = 0; i < 4; i++) {
        uint32_t h, l;
        split_pack(o8[2 * i], o8[2 * i + 1], h, l);
        *(uint32_t*)&g_hh[base + 2 * i] = h;
        *(uint32_t*)&g_hl[base + 2 * i] = l;
    }
}

// ---------------------------------------------------------------------------
// Flash attention: 512 threads, 16 warps x 16 query rows.
// ---------------------------------------------------------------------------
#define QH_OFF 0
#define QL_OFF 32768
#define KH_OFF 65536
#define KL_OFF 98304
#define VT_OFF 131072
#define ATT_SMEM 163840

__global__ __launch_bounds__(512, 1) void k_attn(const int* __restrict__ sl) {
    extern __shared__ char smc[];
    const uint32_t su = smem_u32(smc);
    int b = g_order[blockIdx.x], h = blockIdx.y;
    int L = sl[b], start = g_starts[b], hoff = h * CHD;
    int tid = threadIdx.x;
    int nch = (L + 63) >> 6, RR = nch * 64;

    {
        const __nv_bfloat16* sp[4] = {g_Qh, g_Ql, g_Kh, g_Kl};
        const uint32_t dst[4] = {QH_OFF, QL_OFF, KH_OFF, KL_OFF};
#pragma unroll
        for (int arr = 0; arr < 4; arr++) {
#pragma unroll 1
            for (int u = tid; u < RR * 8; u += 512) {
                int row = u >> 3, g8 = u & 7;
                int rsrc = min(row, L - 1);
                const void* src = sp[arr] + (size_t)(start + rsrc) * CD + hoff + g8 * 8;
                cp16z(su + dst[arr] + swz((uint32_t)(row * 128 + g8 * 16)), src, row < L);
            }
        }
        CP_COMMIT();
    }
#pragma unroll 1
    for (int u = tid; u < RR * 8; u += 512) {
        int row = u >> 3, g8 = u & 7;
        int d0 = g8 * 8;
        uint4 x = make_uint4(0, 0, 0, 0);
        if (row < L)
            x = *(const uint4*)(g_Vb + (size_t)(start + row) * CD + hoff + d0);
        const __nv_bfloat16* pv = (const __nv_bfloat16*)&x;
        uint32_t cb = VT_OFF + (row >> 6) * 8192;
        int kin2 = (row & 63) * 2;
#pragma unroll
        for (int i = 0; i < 8; i++)
            *(__nv_bfloat16*)(smc + cb + swz((uint32_t)((d0 + i) * 128 + kin2))) = pv[i];
    }
    CP_WAIT0();
    __syncthreads();

    int w = tid >> 5, lane = tid & 31;
    int q0w = w * 16;
    if (q0w >= L) return;

    float O[8][4];
#pragma unroll
    for (int nt = 0; nt < 8; nt++)
#pragma unroll
        for (int e = 0; e < 4; e++) O[nt][e] = 0.f;
    float m_run[2] = {0.f, 0.f};
    float l_run[2] = {1.f, 1.f};

#pragma unroll 1
    for (int c = 0; c < nch; c++) {
        int j0 = c * 64;
        float S[8][4];
#pragma unroll
        for (int nt = 0; nt < 8; nt++)
#pragma unroll
            for (int e = 0; e < 4; e++) S[nt][e] = 0.f;

#pragma unroll
        for (int ks = 0; ks < 4; ks++) {
            uint32_t aH[4], aL[4];
            uint32_t ao = swz((uint32_t)((q0w + (lane & 15)) * 128 +
                                         (lane >> 4) * 16 + ks * 32));
            ldsm4(aH, su + QH_OFF + ao);
            ldsm4(aL, su + QL_OFF + ao);
#pragma unroll
            for (int p = 0; p < 4; p++) {
                uint32_t bo_ = swz((uint32_t)((j0 + p * 16 + ((lane >> 4) << 3) + (lane & 7)) * 128 +
                                              ((lane >> 3) & 1) * 16 + ks * 32));
                uint32_t bh[4], bl[4];
                ldsm4(bh, su + KH_OFF + bo_);
                ldsm4(bl, su + KL_OFF + bo_);
                mma_bf16(S[2 * p], aH, bh[0], bh[1]);
                mma_bf16(S[2 * p + 1], aH, bh[2], bh[3]);
                mma_bf16(S[2 * p], aL, bh[0], bh[1]);
                mma_bf16(S[2 * p + 1], aL, bh[2], bh[3]);
                mma_bf16(S[2 * p], aH, bl[0], bl[1]);
                mma_bf16(S[2 * p + 1], aH, bl[2], bl[3]);
            }
        }

        int col01 = j0 + (lane & 3) * 2;
#pragma unroll
        for (int nt = 0; nt < 8; nt++) {
            int base = col01 + nt * 8;
            if (base >= L)     { S[nt][0] = -1e30f; S[nt][2] = -1e30f; }
            if (base + 1 >= L) { S[nt][1] = -1e30f; S[nt][3] = -1e30f; }
        }
        float rmA = -1e30f, rmB = -1e30f;
#pragma unroll
        for (int nt = 0; nt < 8; nt++) {
            rmA = fmaxf(rmA, fmaxf(S[nt][0], S[nt][1]));
            rmB = fmaxf(rmB, fmaxf(S[nt][2], S[nt][3]));
        }
        rmA = q2max(rmA); rmB = q2max(rmB);
        float mA = fmaxf(m_run[0], rmA), mB = fmaxf(m_run[1], rmB);
        float aA = __expf(m_run[0] - mA), aB = __expf(m_run[1] - mB);
        m_run[0] = mA; m_run[1] = mB;
        float sA = 0.f, sB = 0.f;
#pragma unroll
        for (int nt = 0; nt < 8; nt++) {
            S[nt][0] = __expf(S[nt][0] - mA);
            S[nt][1] = __expf(S[nt][1] - mA);
            S[nt][2] = __expf(S[nt][2] - mB);
            S[nt][3] = __expf(S[nt][3] - mB);
            sA += S[nt][0] + S[nt][1];
            sB += S[nt][2] + S[nt][3];
        }
        sA = q2sum(sA); sB = q2sum(sB);
        l_run[0] = l_run[0] * aA + sA;
        l_run[1] = l_run[1] * aB + sB;
#pragma unroll
        for (int nt = 0; nt < 8; nt++) {
            O[nt][0] *= aA; O[nt][1] *= aA;
            O[nt][2] *= aB; O[nt][3] *= aB;
        }

#pragma unroll
        for (int pt = 0; pt < 4; pt++) {
            uint32_t pa[4], pl[4];
            split_pack(S[2 * pt][0], S[2 * pt][1], pa[0], pl[0]);
            split_pack(S[2 * pt][2], S[2 * pt][3], pa[1], pl[1]);
            split_pack(S[2 * pt + 1][0], S[2 * pt + 1][1], pa[2], pl[2]);
            split_pack(S[2 * pt + 1][2], S[2 * pt + 1][3], pa[3], pl[3]);
#pragma unroll
            for (int np = 0; np < 4; np++) {
                uint32_t vo = swz((uint32_t)((np * 16 + ((lane >> 4) << 3) + (lane & 7)) * 128 +
                                             ((lane >> 3) & 1) * 16 + pt * 32));
                uint32_t vb[4];
                ldsm4(vb, su + VT_OFF + c * 8192 + vo);
                mma_bf16(O[2 * np], pa, vb[0], vb[1]);
                mma_bf16(O[2 * np + 1], pa, vb[2], vb[3]);
                mma_bf16(O[2 * np], pl, vb[0], vb[1]);
                mma_bf16(O[2 * np + 1], pl, vb[2], vb[3]);
            }
        }
    }

#pragma unroll
    for (int e2 = 0; e2 < 2; e2++) {
        float iv = 1.f / l_run[e2];
        int r = q0w + e2 * 8 + (lane >> 2);
        if (r >= L) continue;
        size_t rbase = (size_t)(start + r) * CD + hoff;
#pragma unroll
        for (int nt = 0; nt < 8; nt++) {
            int col = nt * 8 + (lane & 3) * 2;
            uint32_t hh, ll;
            split_pack(O[nt][2 * e2] * iv, O[nt][2 * e2 + 1] * iv, hh, ll);
            *(uint32_t*)&g_ch[rbase + col] = hh;
            *(uint32_t*)&g_cl[rbase + col] = ll;
        }
    }
}

// ---------------------------------------------------------------------------
extern "C" void kernel_launch(void* const* d_in, const int* in_sizes, int n_in,
                              void* d_out, int out_size) {
    const float* qe  = (const float*)d_in[0];
    const float* ke  = (const float*)d_in[1];
    const float* ve  = (const float*)d_in[2];
    const float* pt  = (const float*)d_in[3];
    const float* wq  = (const float*)d_in[4];
    const float* bq  = (const float*)d_in[5];
    const float* wk  = (const float*)d_in[6];
    const float* bk  = (const float*)d_in[7];
    const float* wv  = (const float*)d_in[8];
    const float* bv  = (const float*)d_in[9];
    const float* wo  = (const float*)d_in[10];
    const float* bo  = (const float*)d_in[11];
    const float* lng = (const float*)d_in[12];
    const float* lnb = (const float*)d_in[13];
    const float* wm  = (const float*)d_in[14];
    const float* bm  = (const float*)d_in[15];
    const int*   sl  = (const int*)d_in[16];
    float* out = (float*)d_out;

    cudaFuncSetAttribute(k_proj, cudaFuncAttributeMaxDynamicSharedMemorySize, SMEM_P);
    cudaFuncSetAttribute(k_gemm2<1>, cudaFuncAttributeMaxDynamicSharedMemorySize, SMEM_G3);
    cudaFuncSetAttribute(k_gemm2<2>, cudaFuncAttributeMaxDynamicSharedMemorySize, SMEM_G3);
    cudaFuncSetAttribute(k_attn, cudaFuncAttributeMaxDynamicSharedMemorySize, ATT_SMEM);

    k_index<<<1, CB>>>(sl);
    k_wt<<<dim3(16, 8, 5), dim3(32, 8)>>>(wq, wk, wv, wo, wm);

    k_proj<<<dim3(GBX, 2, 3), 512, SMEM_P>>>(qe, ke, ve, pt, bq, bk, bv);
    k_attn<<<dim3(CB, CH), 512, ATT_SMEM>>>(sl);
    k_gemm2<1><<<dim3(GBX, 2), 512, SMEM_G3>>>(nullptr, nullptr);
    k_ln<<<CL1 / 8, 256>>>(bo, lng, lnb);
    k_gemm2<2><<<dim3(GBX, 2), 512, SMEM_G3>>>(bm, out);
}

// round 9
// speedup vs baseline: 2.5689x; 1.0079x over previous
#include <cuda_runtime.h>
#include <cuda_bf16.h>
#include <math.h>
#include <stdint.h>

#define CL1 32896
#define CB  256
#define CD  256
#define CH  4
#define CHD 64
#define TM  128
#define GBX 257

__device__ int   g_starts[CB];
__device__ int   g_pos[CL1];
__device__ int   g_order[CB];
__device__ float g_qc[CL1 * CD];
__device__ float g_tmp[CL1 * CD];
__device__ __nv_bfloat16 g_Qh[CL1 * CD], g_Ql[CL1 * CD];
__device__ __nv_bfloat16 g_Kh[CL1 * CD], g_Kl[CL1 * CD];
__device__ __nv_bfloat16 g_Vb[CL1 * CD];
__device__ __nv_bfloat16 g_qch[CL1 * CD], g_qcl[CL1 * CD];
__device__ __nv_bfloat16 g_ch[CL1 * CD], g_cl[CL1 * CD];
__device__ __nv_bfloat16 g_hh[CL1 * CD], g_hl[CL1 * CD];
__device__ __nv_bfloat16 g_wtq_h[CD * CD], g_wtq_l[CD * CD];
__device__ __nv_bfloat16 g_wtk_h[CD * CD], g_wtk_l[CD * CD];
__device__ __nv_bfloat16 g_wtv_h[CD * CD], g_wtv_l[CD * CD];
__device__ __nv_bfloat16 g_wto_h[CD * CD], g_wto_l[CD * CD];
__device__ __nv_bfloat16 g_wtm_h[2 * CD * CD], g_wtm_l[2 * CD * CD];

__device__ __forceinline__ uint32_t smem_u32(const void* p) {
    return (uint32_t)__cvta_generic_to_shared(p);
}
__device__ __forceinline__ uint32_t swz(uint32_t off) {
    return off ^ ((off >> 3) & 0x70);
}
__device__ __forceinline__ void ldsm4(uint32_t r[4], uint32_t addr) {
    asm volatile("ldmatrix.sync.aligned.m8n8.x4.shared.b16 {%0,%1,%2,%3}, [%4];"
                 : "=r"(r[0]), "=r"(r[1]), "=r"(r[2]), "=r"(r[3]) : "r"(addr));
}
__device__ __forceinline__ void ldsm4t(uint32_t r[4], uint32_t addr) {
    asm volatile("ldmatrix.sync.aligned.m8n8.x4.trans.shared.b16 {%0,%1,%2,%3}, [%4];"
                 : "=r"(r[0]), "=r"(r[1]), "=r"(r[2]), "=r"(r[3]) : "r"(addr));
}
__device__ __forceinline__ void mma_bf16(float d[4], const uint32_t a[4],
                                         uint32_t b0, uint32_t b1) {
    asm volatile("mma.sync.aligned.m16n8k16.row.col.f32.bf16.bf16.f32 "
                 "{%0,%1,%2,%3}, {%4,%5,%6,%7}, {%8,%9}, {%0,%1,%2,%3};"
                 : "+f"(d[0]), "+f"(d[1]), "+f"(d[2]), "+f"(d[3])
                 : "r"(a[0]), "r"(a[1]), "r"(a[2]), "r"(a[3]), "r"(b0), "r"(b1));
}
__device__ __forceinline__ void split_pack(float a, float b, uint32_t& h, uint32_t& l) {
    __nv_bfloat16 ha = __float2bfloat16_rn(a), hb = __float2bfloat16_rn(b);
    __nv_bfloat162 H = __halves2bfloat162(ha, hb);
    h = *(uint32_t*)&H;
    __nv_bfloat162 Lo = __float22bfloat162_rn(
        make_float2(a - __bfloat162float(ha), b - __bfloat162float(hb)));
    l = *(uint32_t*)&Lo;
}
__device__ __forceinline__ float q2max(float v) {
    v = fmaxf(v, __shfl_xor_sync(0xffffffffu, v, 1));
    return fmaxf(v, __shfl_xor_sync(0xffffffffu, v, 2));
}
__device__ __forceinline__ float q2sum(float v) {
    v += __shfl_xor_sync(0xffffffffu, v, 1);
    return v + __shfl_xor_sync(0xffffffffu, v, 2);
}
__device__ __forceinline__ void cp16(uint32_t dst, const void* src) {
    asm volatile("cp.async.cg.shared.global [%0], [%1], 16;" :: "r"(dst), "l"(src));
}
__device__ __forceinline__ void cp16z(uint32_t dst, const void* src, int do_copy) {
    asm volatile("cp.async.cg.shared.global [%0], [%1], 16, %2;"
                 :: "r"(dst), "l"(src), "r"(do_copy ? 16 : 0));
}
#define CP_COMMIT() asm volatile("cp.async.commit_group;" ::: "memory")
#define CP_WAIT2()  asm volatile("cp.async.wait_group 2;" ::: "memory")
#define CP_WAIT1()  asm volatile("cp.async.wait_group 1;" ::: "memory")
#define CP_WAIT0()  asm volatile("cp.async.wait_group 0;" ::: "memory")

// ---------------------------------------------------------------------------
__global__ void k_index(const int* __restrict__ sl) {
    __shared__ int st[CB];
    int tid = threadIdx.x;
    if (tid == 0) {
        int a = 0;
        for (int b = 0; b < CB; b++) { st[b] = a; a += sl[b]; }
    }
    __syncthreads();
    int s = st[tid], len = sl[tid];
    g_starts[tid] = s;
    g_order[CB - len] = tid;
    for (int i = 0; i < len; i++) g_pos[s + i] = i;
}

__global__ void k_wt(const float* __restrict__ wq, const float* __restrict__ wk,
                     const float* __restrict__ wv, const float* __restrict__ wo,
                     const float* __restrict__ wm) {
    __shared__ float t[32][33];
    int z = blockIdx.z;
    const float* W; __nv_bfloat16* oh; __nv_bfloat16* ol; int K;
    switch (z) {
        case 0: W = wq; oh = g_wtq_h; ol = g_wtq_l; K = 256; break;
        case 1: W = wk; oh = g_wtk_h; ol = g_wtk_l; K = 256; break;
        case 2: W = wv; oh = g_wtv_h; ol = g_wtv_l; K = 256; break;
        case 3: W = wo; oh = g_wto_h; ol = g_wto_l; K = 256; break;
        default: W = wm; oh = g_wtm_h; ol = g_wtm_l; K = 512; break;
    }
    int k0 = blockIdx.x * 32, n0 = blockIdx.y * 32;
    if (k0 >= K) return;
    int tx = threadIdx.x, ty = threadIdx.y;
#pragma unroll
    for (int i = 0; i < 4; i++)
        t[ty + 8 * i][tx] = W[(size_t)(k0 + ty + 8 * i) * CD + n0 + tx];
    __syncthreads();
#pragma unroll
    for (int i = 0; i < 4; i++) {
        int rr = ty + 8 * i;
        float v = t[tx][rr];
        __nv_bfloat16 h = __float2bfloat16_rn(v);
        oh[(size_t)(n0 + rr) * K + k0 + tx] = h;
        ol[(size_t)(n0 + rr) * K + k0 + tx] = __float2bfloat16_rn(v - __bfloat162float(h));
    }
}

// ---------------------------------------------------------------------------
#define STG 65536
#define SMEM_P (2 * STG)
#define SMEM_G3 (3 * STG)

// Projections: z = 0(Q) 1(K) 2(V)
__global__ __launch_bounds__(512, 1) void k_proj(
    const float* __restrict__ qe, const float* __restrict__ ke,
    const float* __restrict__ ve, const float* __restrict__ pt,
    const float* __restrict__ bq, const float* __restrict__ bk,
    const float* __restrict__ bv) {
    extern __shared__ char smc[];
    const uint32_t su = smem_u32(smc);
    const int z = blockIdx.z;
    const float* emb = z == 0 ? qe : (z == 1 ? ke : ve);
    const __nv_bfloat16* Bh_g = z == 0 ? g_wtq_h : (z == 1 ? g_wtk_h : g_wtv_h);
    const __nv_bfloat16* Bl_g = z == 0 ? g_wtq_l : (z == 1 ? g_wtk_l : g_wtv_l);
    const float* bias = z == 0 ? bq : (z == 1 ? bk : bv);
    const int shift = (z == 0) ? 1 : 0;
    const bool saveq = (z == 0);
    const int t0 = blockIdx.x * TM, n0 = blockIdx.y * 128;
    const int tid = threadIdx.x, w = tid >> 5, lane = tid & 31;
    const int mw = (w & 3) * 32, nw = (w >> 2) * 32;

    __shared__ int spos[TM];
    if (tid < TM) spos[tid] = g_pos[t0 + tid];
    __syncthreads();

    float acc[2][4][4];
#pragma unroll
    for (int i = 0; i < 2; i++)
#pragma unroll
        for (int j = 0; j < 4; j++)
#pragma unroll
            for (int q = 0; q < 4; q++) acc[i][j][q] = 0.f;

    const uint4* Bh4 = (const uint4*)Bh_g;
    const uint4* Bl4 = (const uint4*)Bl_g;
    float4 aR[4];
    uint4 bhR[2], blR[2];

    auto ldA = [&](int kc) {
        int k0a = kc * 64;
#pragma unroll
        for (int i = 0; i < 4; i++) {
            int u = i * 512 + tid;
            int row = u >> 4, f4 = u & 15;
            int t = t0 + row;
            float4 x = *(const float4*)(emb + (size_t)t * CD + k0a + f4 * 4);
            float4 p4 = *(const float4*)(pt + (size_t)(spos[row] + shift) * CD + k0a + f4 * 4);
            x.x += p4.x; x.y += p4.y; x.z += p4.z; x.w += p4.w;
            if (saveq) {
                size_t gi = (size_t)t * CD + k0a + f4 * 4;
                *(float4*)(g_qc + gi) = x;
                uint32_t h01, l01, h23, l23;
                split_pack(x.x, x.y, h01, l01);
                split_pack(x.z, x.w, h23, l23);
                *(uint32_t*)&g_qch[gi] = h01; *(uint32_t*)&g_qch[gi + 2] = h23;
                *(uint32_t*)&g_qcl[gi] = l01; *(uint32_t*)&g_qcl[gi + 2] = l23;
            }
            aR[i] = x;
        }
    };
    auto ldB = [&](int kc) {
#pragma unroll
        for (int i = 0; i < 2; i++) {
            int u = i * 512 + tid;
            int n = u >> 3, kb16 = u & 7;
            size_t gi = (((size_t)(n0 + n) * 256 + kc * 64) >> 3) + kb16;
            bhR[i] = Bh4[gi];
            blR[i] = Bl4[gi];
        }
    };
    auto sts = [&](int s) {
        char* sb = smc + s * STG;
#pragma unroll
        for (int i = 0; i < 4; i++) {
            int u = i * 512 + tid;
            int row = u >> 4, f4 = u & 15;
            float4 x = aR[i];
            uint32_t h01, l01, h23, l23;
            split_pack(x.x, x.y, h01, l01);
            split_pack(x.z, x.w, h23, l23);
            uint32_t off = swz((uint32_t)(row * 128 + f4 * 8));
            *(uint2*)(sb + off) = make_uint2(h01, h23);
            *(uint2*)(sb + 16384 + off) = make_uint2(l01, l23);
        }
#pragma unroll
        for (int i = 0; i < 2; i++) {
            int u = i * 512 + tid;
            int n = u >> 3, kb16 = u & 7;
            uint32_t off = swz((uint32_t)(n * 128 + kb16 * 16));
            *(uint4*)(sb + 32768 + off) = bhR[i];
            *(uint4*)(sb + 49152 + off) = blR[i];
        }
    };

    ldA(0); ldB(0);
#pragma unroll 1
    for (int kc = 0; kc < 4; kc++) {
        int s = kc & 1;
        sts(s);
        if (kc + 1 < 4) { ldA(kc + 1); ldB(kc + 1); }
        __syncthreads();
        const uint32_t sb = su + s * STG;
        uint32_t arow = (uint32_t)((mw + (lane & 15)) * 128 + (lane >> 4) * 16);
        uint32_t bn = (uint32_t)((nw + ((lane >> 4) << 3) + (lane & 7)) * 128 +
                                 ((lane >> 3) & 1) * 16);
#pragma unroll
        for (int ks = 0; ks < 4; ks++) {
            uint32_t kb = ks * 32;
            uint32_t ah[2][4], al[2][4], bh[2][4], bl[2][4];
#pragma unroll
            for (int mt = 0; mt < 2; mt++) {
                uint32_t a = sb + swz(arow + mt * 16 * 128 + kb);
                ldsm4(ah[mt], a);
                ldsm4(al[mt], a + 16384);
            }
#pragma unroll
            for (int nc = 0; nc < 2; nc++) {
                uint32_t a = sb + 32768 + swz(bn + nc * 16 * 128 + kb);
                ldsm4(bh[nc], a);
                ldsm4(bl[nc], a + 16384);
            }
#pragma unroll
            for (int mt = 0; mt < 2; mt++)
#pragma unroll
                for (int nc = 0; nc < 2; nc++) {
                    mma_bf16(acc[mt][nc * 2 + 0], ah[mt], bh[nc][0], bh[nc][1]);
                    mma_bf16(acc[mt][nc * 2 + 1], ah[mt], bh[nc][2], bh[nc][3]);
                    mma_bf16(acc[mt][nc * 2 + 0], al[mt], bh[nc][0], bh[nc][1]);
                    mma_bf16(acc[mt][nc * 2 + 1], al[mt], bh[nc][2], bh[nc][3]);
                    mma_bf16(acc[mt][nc * 2 + 0], ah[mt], bl[nc][0], bl[nc][1]);
                    mma_bf16(acc[mt][nc * 2 + 1], ah[mt], bl[nc][2], bl[nc][3]);
                }
        }
    }

#pragma unroll
    for (int mt = 0; mt < 2; mt++) {
#pragma unroll
        for (int nt = 0; nt < 4; nt++) {
            int row = t0 + mw + mt * 16 + (lane >> 2);
            int col = n0 + nw + nt * 8 + (lane & 3) * 2;
            float2 b2 = *(const float2*)(bias + col);
            float2 d0 = make_float2(acc[mt][nt][0] + b2.x, acc[mt][nt][1] + b2.y);
            float2 d1 = make_float2(acc[mt][nt][2] + b2.x, acc[mt][nt][3] + b2.y);
            size_t i0 = (size_t)row * CD + col, i1 = (size_t)(row + 8) * CD + col;
            if (z == 0) {
                uint32_t h, l;
                split_pack(d0.x * 0.125f, d0.y * 0.125f, h, l);
                *(uint32_t*)&g_Qh[i0] = h; *(uint32_t*)&g_Ql[i0] = l;
                split_pack(d1.x * 0.125f, d1.y * 0.125f, h, l);
                *(uint32_t*)&g_Qh[i1] = h; *(uint32_t*)&g_Ql[i1] = l;
            } else if (z == 1) {
                uint32_t h, l;
                split_pack(d0.x, d0.y, h, l);
                *(uint32_t*)&g_Kh[i0] = h; *(uint32_t*)&g_Kl[i0] = l;
                split_pack(d1.x, d1.y, h, l);
                *(uint32_t*)&g_Kh[i1] = h; *(uint32_t*)&g_Kl[i1] = l;
            } else {
                __nv_bfloat162 v0 = __float22bfloat162_rn(d0);
                __nv_bfloat162 v1 = __float22bfloat162_rn(d1);
                *(uint32_t*)&g_Vb[i0] = *(uint32_t*)&v0;
                *(uint32_t*)&g_Vb[i1] = *(uint32_t*)&v1;
            }
        }
    }
}

// ---------------------------------------------------------------------------
template <int MODE>
__global__ __launch_bounds__(512, 1) void k_gemm2(
    const float* __restrict__ bias, float* __restrict__ outp) {
    extern __shared__ char smc[];
    const uint32_t su = smem_u32(smc);
    constexpr int KW = (MODE == 2) ? 512 : 256;
    constexpr int NCH = KW / 64;
    const int t0 = blockIdx.x * TM, n0 = blockIdx.y * 128;
    const int tid = threadIdx.x, w = tid >> 5, lane = tid & 31;
    const int mw = (w & 3) * 32, nw = (w >> 2) * 32;

    auto issue = [&](int kc) {
        uint32_t sb = su + (kc % 3) * STG;
        const __nv_bfloat16 *Ah_g, *Al_g;
        int k0a;
        if (MODE == 2) {
            Ah_g = (kc < 4) ? g_hh : g_qch;
            Al_g = (kc < 4) ? g_hl : g_qcl;
            k0a = (kc & 3) * 64;
        } else { Ah_g = g_ch; Al_g = g_cl; k0a = kc * 64; }
#pragma unroll
        for (int i = 0; i < 2; i++) {
            int u = i * 512 + tid;
            int row = u >> 3, g8 = u & 7;
            size_t so = (size_t)(t0 + row) * CD + k0a + g8 * 8;
            uint32_t off = swz((uint32_t)(row * 128 + g8 * 16));
            cp16(sb + off, Ah_g + so);
            cp16(sb + 16384 + off, Al_g + so);
        }
        const __nv_bfloat16* Bh_g = (MODE == 2) ? g_wtm_h : g_wto_h;
        const __nv_bfloat16* Bl_g = (MODE == 2) ? g_wtm_l : g_wto_l;
#pragma unroll
        for (int i = 0; i < 2; i++) {
            int u = i * 512 + tid;
            int n = u >> 3, g8 = u & 7;
            size_t so = (size_t)(n0 + n) * KW + kc * 64 + g8 * 8;
            uint32_t off = swz((uint32_t)(n * 128 + g8 * 16));
            cp16(sb + 32768 + off, Bh_g + so);
            cp16(sb + 49152 + off, Bl_g + so);
        }
    };

    float acc[2][4][4];
#pragma unroll
    for (int i = 0; i < 2; i++)
#pragma unroll
        for (int j = 0; j < 4; j++)
#pragma unroll
            for (int q = 0; q < 4; q++) acc[i][j][q] = 0.f;

    issue(0); CP_COMMIT();
    issue(1); CP_COMMIT();
#pragma unroll 1
    for (int kc = 0; kc < NCH; kc++) {
        CP_WAIT1();
        __syncthreads();
        if (kc + 2 < NCH) issue(kc + 2);
        CP_COMMIT();
        const uint32_t sb = su + (kc % 3) * STG;
        uint32_t arow = (uint32_t)((mw + (lane & 15)) * 128 + (lane >> 4) * 16);
        uint32_t bn = (uint32_t)((nw + ((lane >> 4) << 3) + (lane & 7)) * 128 +
                                 ((lane >> 3) & 1) * 16);
#pragma unroll
        for (int ks = 0; ks < 4; ks++) {
            uint32_t kb = ks * 32;
            uint32_t ah[2][4], al[2][4], bh[2][4], bl[2][4];
#pragma unroll
            for (int mt = 0; mt < 2; mt++) {
                uint32_t a = sb + swz(arow + mt * 16 * 128 + kb);
                ldsm4(ah[mt], a);
                ldsm4(al[mt], a + 16384);
            }
#pragma unroll
            for (int nc = 0; nc < 2; nc++) {
                uint32_t a = sb + 32768 + swz(bn + nc * 16 * 128 + kb);
                ldsm4(bh[nc], a);
                ldsm4(bl[nc], a + 16384);
            }
#pragma unroll
            for (int mt = 0; mt < 2; mt++)
#pragma unroll
                for (int nc = 0; nc < 2; nc++) {
                    mma_bf16(acc[mt][nc * 2 + 0], ah[mt], bh[nc][0], bh[nc][1]);
                    mma_bf16(acc[mt][nc * 2 + 1], ah[mt], bh[nc][2], bh[nc][3]);
                    mma_bf16(acc[mt][nc * 2 + 0], al[mt], bh[nc][0], bh[nc][1]);
                    mma_bf16(acc[mt][nc * 2 + 1], al[mt], bh[nc][2], bh[nc][3]);
                    mma_bf16(acc[mt][nc * 2 + 0], ah[mt], bl[nc][0], bl[nc][1]);
                    mma_bf16(acc[mt][nc * 2 + 1], ah[mt], bl[nc][2], bl[nc][3]);
                }
        }
    }

    float* op = (MODE == 1) ? g_tmp : outp;
    const float r2 = 0.70710678118654752440f;
#pragma unroll
    for (int mt = 0; mt < 2; mt++) {
#pragma unroll
        for (int nt = 0; nt < 4; nt++) {
            int row = t0 + mw + mt * 16 + (lane >> 2);
            int col = n0 + nw + nt * 8 + (lane & 3) * 2;
            float2 d0 = make_float2(acc[mt][nt][0], acc[mt][nt][1]);
            float2 d1 = make_float2(acc[mt][nt][2], acc[mt][nt][3]);
            if (MODE == 2) {
                float2 b2 = *(const float2*)(bias + col);
                d0.x += b2.x; d0.y += b2.y;
                d1.x += b2.x; d1.y += b2.y;
                d0.x = 0.5f * d0.x * (1.f + erff(d0.x * r2));
                d0.y = 0.5f * d0.y * (1.f + erff(d0.y * r2));
                d1.x = 0.5f * d1.x * (1.f + erff(d1.x * r2));
                d1.y = 0.5f * d1.y * (1.f + erff(d1.y * r2));
            }
            *(float2*)(op + (size_t)row * CD + col) = d0;
            *(float2*)(op + (size_t)(row + 8) * CD + col) = d1;
        }
    }
}

// ---------------------------------------------------------------------------
__global__ __launch_bounds__(256) void k_ln(
    const float* __restrict__ bo, const float* __restrict__ lng,
    const float* __restrict__ lnb) {
    int w = threadIdx.x >> 5, lane = threadIdx.x & 31;
    int r = blockIdx.x * 8 + w;
    int c0 = lane * 8;
    float4 t0 = *(const float4*)(g_tmp + (size_t)r * CD + c0);
    float4 t1 = *(const float4*)(g_tmp + (size_t)r * CD + c0 + 4);
    float4 q0 = *(const float4*)(g_qc + (size_t)r * CD + c0);
    float4 q1 = *(const float4*)(g_qc + (size_t)r * CD + c0 + 4);
    float4 b0 = *(const float4*)(bo + c0);
    float4 b1 = *(const float4*)(bo + c0 + 4);
    float v[8];
    v[0] = t0.x + q0.x + b0.x; v[1] = t0.y + q0.y + b0.y;
    v[2] = t0.z + q0.z + b0.z; v[3] = t0.w + q0.w + b0.w;
    v[4] = t1.x + q1.x + b1.x; v[5] = t1.y + q1.y + b1.y;
    v[6] = t1.z + q1.z + b1.z; v[7] = t1.w + q1.w + b1.w;
    float s1 = 0.f, s2 = 0.f;
#pragma unroll
    for (int i = 0; i < 8; i++) { s1 += v[i]; s2 += v[i] * v[i]; }
#pragma unroll
    for (int o = 16; o; o >>= 1) {
        s1 += __shfl_xor_sync(0xffffffffu, s1, o);
        s2 += __shfl_xor_sync(0xffffffffu, s2, o);
    }
    float mu = s1 * (1.f / CD);
    float rs = rsqrtf(s2 * (1.f / CD) - mu * mu + 1e-12f);
    float4 g0 = *(const float4*)(lng + c0);
    float4 g1 = *(const float4*)(lng + c0 + 4);
    float4 bb0 = *(const float4*)(lnb + c0);
    float4 bb1 = *(const float4*)(lnb + c0 + 4);
    float o8[8];
    o8[0] = (v[0] - mu) * rs * g0.x + bb0.x; o8[1] = (v[1] - mu) * rs * g0.y + bb0.y;
    o8[2] = (v[2] - mu) * rs * g0.z + bb0.z; o8[3] = (v[3] - mu) * rs * g0.w + bb0.w;
    o8[4] = (v[4] - mu) * rs * g1.x + bb1.x; o8[5] = (v[5] - mu) * rs * g1.y + bb1.y;
    o8[6] = (v[6] - mu) * rs * g1.z + bb1.z; o8[7] = (v[7] - mu) * rs * g1.w + bb1.w;
    size_t base = (size_t)r * CD + c0;
#pragma unroll
    for (int i = 0; i < 4; i++) {
        uint32_t h, l;
        split_pack(o8[2 * i], o8[2 * i + 1], h, l);
        *(uint32_t*)&g_hh[base + 2 * i] = h;
        *(uint32_t*)&g_hl[base + 2 * i] = l;
    }
}

// ---------------------------------------------------------------------------
// Flash attention: Q resident (hi/lo), K/V in pipelined 64-key cp.async chunks.
// V consumed key-major via ldmatrix.trans (no explicit transpose).
// ---------------------------------------------------------------------------
#define QH_OFF 0
#define QL_OFF 32768
#define KV_OFF 65536
#define KV_STG 24576      // Kh 8K | Kl 8K | V 8K
#define ATT_SMEM (KV_OFF + 3 * KV_STG)

__global__ __launch_bounds__(512, 1) void k_attn(const int* __restrict__ sl) {
    extern __shared__ char smc[];
    const uint32_t su = smem_u32(smc);
    int b = g_order[blockIdx.x], h = blockIdx.y;
    int L = sl[b], start = g_starts[b], hoff = h * CHD;
    int tid = threadIdx.x;
    int nch = (L + 63) >> 6, RR = nch * 64;

    auto stageKV = [&](int c) {
        uint32_t sb = su + KV_OFF + (c % 3) * KV_STG;
        int r = tid >> 3, g8 = tid & 7;
        int row = c * 64 + r;
        int rs = min(row, L - 1);
        int ok = row < L;
        size_t so = (size_t)(start + rs) * CD + hoff + g8 * 8;
        uint32_t off = swz((uint32_t)(r * 128 + g8 * 16));
        cp16z(sb + off, g_Kh + so, ok);
        cp16z(sb + 8192 + off, g_Kl + so, ok);
        cp16z(sb + 16384 + off, g_Vb + so, ok);
    };

    // Q (hi/lo) staged once
    {
        const __nv_bfloat16* sp[2] = {g_Qh, g_Ql};
        const uint32_t dst[2] = {QH_OFF, QL_OFF};
#pragma unroll
        for (int arr = 0; arr < 2; arr++) {
#pragma unroll 1
            for (int u = tid; u < RR * 8; u += 512) {
                int row = u >> 3, g8 = u & 7;
                int rsrc = min(row, L - 1);
                const void* src = sp[arr] + (size_t)(start + rsrc) * CD + hoff + g8 * 8;
                cp16z(su + dst[arr] + swz((uint32_t)(row * 128 + g8 * 16)), src, row < L);
            }
        }
    }
    stageKV(0); CP_COMMIT();
    if (1 < nch) stageKV(1);
    CP_COMMIT();
    if (2 < nch) stageKV(2);
    CP_COMMIT();

    int w = tid >> 5, lane = tid & 31;
    int q0w = w * 16;
    bool active = q0w < L;

    float O[8][4];
#pragma unroll
    for (int nt = 0; nt < 8; nt++)
#pragma unroll
        for (int e = 0; e < 4; e++) O[nt][e] = 0.f;
    float m_run[2] = {0.f, 0.f};
    float l_run[2] = {1.f, 1.f};

#pragma unroll 1
    for (int c = 0; c < nch; c++) {
        CP_WAIT2();
        __syncthreads();
        const uint32_t kb_base = su + KV_OFF + (c % 3) * KV_STG;

        if (active) {
            int j0 = c * 64;
            float S[8][4];
#pragma unroll
            for (int nt = 0; nt < 8; nt++)
#pragma unroll
                for (int e = 0; e < 4; e++) S[nt][e] = 0.f;

#pragma unroll
            for (int ks = 0; ks < 4; ks++) {
                uint32_t aH[4], aL[4];
                uint32_t ao = swz((uint32_t)((q0w + (lane & 15)) * 128 +
                                             (lane >> 4) * 16 + ks * 32));
                ldsm4(aH, su + QH_OFF + ao);
                ldsm4(aL, su + QL_OFF + ao);
#pragma unroll
                for (int p = 0; p < 4; p++) {
                    uint32_t bo_ = swz((uint32_t)((p * 16 + ((lane >> 4) << 3) + (lane & 7)) * 128 +
                                                  ((lane >> 3) & 1) * 16 + ks * 32));
                    uint32_t bh[4], bl[4];
                    ldsm4(bh, kb_base + bo_);
                    ldsm4(bl, kb_base + 8192 + bo_);
                    mma_bf16(S[2 * p], aH, bh[0], bh[1]);
                    mma_bf16(S[2 * p + 1], aH, bh[2], bh[3]);
                    mma_bf16(S[2 * p], aL, bh[0], bh[1]);
                    mma_bf16(S[2 * p + 1], aL, bh[2], bh[3]);
                    mma_bf16(S[2 * p], aH, bl[0], bl[1]);
                    mma_bf16(S[2 * p + 1], aH, bl[2], bl[3]);
                }
            }

            int col01 = j0 + (lane & 3) * 2;
#pragma unroll
            for (int nt = 0; nt < 8; nt++) {
                int base = col01 + nt * 8;
                if (base >= L)     { S[nt][0] = -1e30f; S[nt][2] = -1e30f; }
                if (base + 1 >= L) { S[nt][1] = -1e30f; S[nt][3] = -1e30f; }
            }
            float rmA = -1e30f, rmB = -1e30f;
#pragma unroll
            for (int nt = 0; nt < 8; nt++) {
                rmA = fmaxf(rmA, fmaxf(S[nt][0], S[nt][1]));
                rmB = fmaxf(rmB, fmaxf(S[nt][2], S[nt][3]));
            }
            rmA = q2max(rmA); rmB = q2max(rmB);
            float mA = fmaxf(m_run[0], rmA), mB = fmaxf(m_run[1], rmB);
            float aA = __expf(m_run[0] - mA), aB = __expf(m_run[1] - mB);
            m_run[0] = mA; m_run[1] = mB;
            float sA = 0.f, sB = 0.f;
#pragma unroll
            for (int nt = 0; nt < 8; nt++) {
                S[nt][0] = __expf(S[nt][0] - mA);
                S[nt][1] = __expf(S[nt][1] - mA);
                S[nt][2] = __expf(S[nt][2] - mB);
                S[nt][3] = __expf(S[nt][3] - mB);
                sA += S[nt][0] + S[nt][1];
                sB += S[nt][2] + S[nt][3];
            }
            sA = q2sum(sA); sB = q2sum(sB);
            l_run[0] = l_run[0] * aA + sA;
            l_run[1] = l_run[1] * aB + sB;
#pragma unroll
            for (int nt = 0; nt < 8; nt++) {
                O[nt][0] *= aA; O[nt][1] *= aA;
                O[nt][2] *= aB; O[nt][3] *= aB;
            }

            // PV: V key-major via ldmatrix.trans
#pragma unroll
            for (int pt = 0; pt < 4; pt++) {
                uint32_t pa[4], pl[4];
                split_pack(S[2 * pt][0], S[2 * pt][1], pa[0], pl[0]);
                split_pack(S[2 * pt][2], S[2 * pt][3], pa[1], pl[1]);
                split_pack(S[2 * pt + 1][0], S[2 * pt + 1][1], pa[2], pl[2]);
                split_pack(S[2 * pt + 1][2], S[2 * pt + 1][3], pa[3], pl[3]);
#pragma unroll
                for (int np = 0; np < 4; np++) {
                    uint32_t vo = swz((uint32_t)((pt * 16 + (lane & 15)) * 128 +
                                                 np * 32 + (lane >> 4) * 16));
                    uint32_t vb[4];
                    ldsm4t(vb, kb_base + 16384 + vo);
                    mma_bf16(O[2 * np], pa, vb[0], vb[1]);
                    mma_bf16(O[2 * np + 1], pa, vb[2], vb[3]);
                    mma_bf16(O[2 * np], pl, vb[0], vb[1]);
                    mma_bf16(O[2 * np + 1], pl, vb[2], vb[3]);
                }
            }
        }
        __syncthreads();
        if (c + 3 < nch) stageKV(c + 3);
        CP_COMMIT();
    }

    if (active) {
#pragma unroll
        for (int e2 = 0; e2 < 2; e2++) {
            float iv = 1.f / l_run[e2];
            int r = q0w + e2 * 8 + (lane >> 2);
            if (r >= L) continue;
            size_t rbase = (size_t)(start + r) * CD + hoff;
#pragma unroll
            for (int nt = 0; nt < 8; nt++) {
                int col = nt * 8 + (lane & 3) * 2;
                uint32_t hh, ll;
                split_pack(O[nt][2 * e2] * iv, O[nt][2 * e2 + 1] * iv, hh, ll);
                *(uint32_t*)&g_ch[rbase + col] = hh;
                *(uint32_t*)&g_cl[rbase + col] = ll;
            }
        }
    }
}

// ---------------------------------------------------------------------------
extern "C" void kernel_launch(void* const* d_in, const int* in_sizes, int n_in,
                              void* d_out, int out_size) {
    const float* qe  = (const float*)d_in[0];
    const float* ke  = (const float*)d_in[1];
    const float* ve  = (const float*)d_in[2];
    const float* pt  = (const float*)d_in[3];
    const float* wq  = (const float*)d_in[4];
    const float* bq  = (const float*)d_in[5];
    const float* wk  = (const float*)d_in[6];
    const float* bk  = (const float*)d_in[7];
    const float* wv  = (const float*)d_in[8];
    const float* bv  = (const float*)d_in[9];
    const float* wo  = (const float*)d_in[10];
    const float* bo  = (const float*)d_in[11];
    const float* lng = (const float*)d_in[12];
    const float* lnb = (const float*)d_in[13];
    const float* wm  = (const float*)d_in[14];
    const float* bm  = (const float*)d_in[15];
    const int*   sl  = (const int*)d_in[16];
    float* out = (float*)d_out;

    cudaFuncSetAttribute(k_proj, cudaFuncAttributeMaxDynamicSharedMemorySize, SMEM_P);
    cudaFuncSetAttribute(k_gemm2<1>, cudaFuncAttributeMaxDynamicSharedMemorySize, SMEM_G3);
    cudaFuncSetAttribute(k_gemm2<2>, cudaFuncAttributeMaxDynamicSharedMemorySize, SMEM_G3);
    cudaFuncSetAttribute(k_attn, cudaFuncAttributeMaxDynamicSharedMemorySize, ATT_SMEM);

    k_index<<<1, CB>>>(sl);
    k_wt<<<dim3(16, 8, 5), dim3(32, 8)>>>(wq, wk, wv, wo, wm);

    k_proj<<<dim3(GBX, 2, 3), 512, SMEM_P>>>(qe, ke, ve, pt, bq, bk, bv);
    k_attn<<<dim3(CB, CH), 512, ATT_SMEM>>>(sl);
    k_gemm2<1><<<dim3(GBX, 2), 512, SMEM_G3>>>(nullptr, nullptr);
    k_ln<<<CL1 / 8, 256>>>(bo, lng, lnb);
    k_gemm2<2><<<dim3(GBX, 2), 512, SMEM_G3>>>(bm, out);
}